// round 1
// baseline (speedup 1.0000x reference)
#include <cuda_runtime.h>
#include <cuda_bf16.h>
#include <math.h>

// ---------------- problem constants ----------------
#define Bt   8
#define Nt   384
#define Dt   512
#define Ht   8
#define DEt  32
#define DFt  2048
#define DKt  64
#define BN   (Bt*Nt)            // 3072
#define NN   (Nt*Nt)            // 147456

// scratch layout (floats)
#define OFF_NX     0LL
#define OFF_Q      (OFF_NX    + (long long)BN*Dt)
#define OFF_K      (OFF_Q     + (long long)BN*Dt)
#define OFF_V      (OFF_K     + (long long)BN*Dt)
#define OFF_KEDGE  (OFF_V     + (long long)BN*Dt)
#define OFF_BIAS   (OFF_KEDGE + (long long)Bt*NN*DEt)
#define OFF_ATTN   (OFF_BIAS  + (long long)Bt*NN)
#define OFF_CTX    (OFF_ATTN  + (long long)Bt*Ht*NN)
#define OFF_ECTX   (OFF_CTX   + (long long)BN*Dt)
#define OFF_ECTXO  (OFF_ECTX  + (long long)BN*Ht*DEt)
#define OFF_X1     (OFF_ECTXO + (long long)BN*Dt)
#define OFF_NX2    (OFF_X1    + (long long)BN*Dt)
#define OFF_H1     (OFF_NX2   + (long long)BN*Dt)
#define SCRATCH_TOTAL (OFF_H1 + (long long)BN*DFt)   // 68,026,368 floats

static __device__ float g_scratch[SCRATCH_TOTAL];

// ---------------- helpers ----------------
__device__ __forceinline__ float gelu_f(float v) {
    float t3 = v * v * v;
    return 0.5f * v * (1.0f + tanhf(0.7978845608028654f * (v + 0.044715f * t3)));
}

// block reduce for blockDim.x = 128 (4 warps)
__device__ __forceinline__ float blockReduce128(float v, bool isMax, float* sh) {
    #pragma unroll
    for (int o = 16; o; o >>= 1) {
        float o2 = __shfl_xor_sync(0xffffffffu, v, o);
        v = isMax ? fmaxf(v, o2) : v + o2;
    }
    __syncthreads();
    if ((threadIdx.x & 31) == 0) sh[threadIdx.x >> 5] = v;
    __syncthreads();
    float r = sh[0];
    #pragma unroll
    for (int k = 1; k < 4; k++) r = isMax ? fmaxf(r, sh[k]) : r + sh[k];
    return r;
}

// ---------------- LayerNorm over 512 cols ----------------
__global__ __launch_bounds__(128) void ln512_kernel(
    const float* __restrict__ in, const float* __restrict__ g,
    const float* __restrict__ b, float* __restrict__ out)
{
    __shared__ float sh[4];
    int row = blockIdx.x;
    int t = threadIdx.x;
    const float4* inr = (const float4*)(in + (size_t)row * Dt);
    float4 v = inr[t];
    float s  = v.x + v.y + v.z + v.w;
    float sq = v.x*v.x + v.y*v.y + v.z*v.z + v.w*v.w;
    // combined reduce: first sum
    float tot = blockReduce128(s, false, sh);
    __syncthreads();
    float totq = blockReduce128(sq, false, sh);
    float mean = tot * (1.0f / Dt);
    float var  = totq * (1.0f / Dt) - mean * mean;
    float inv  = rsqrtf(var + 1e-5f);
    float4 gg = ((const float4*)g)[t];
    float4 bb = ((const float4*)b)[t];
    float4 o;
    o.x = (v.x - mean) * inv * gg.x + bb.x;
    o.y = (v.y - mean) * inv * gg.y + bb.y;
    o.z = (v.z - mean) * inv * gg.z + bb.z;
    o.w = (v.w - mean) * inv * gg.w + bb.w;
    ((float4*)(out + (size_t)row * Dt))[t] = o;
}

// ---------------- fused edge LN + Wke proj + scalar bias ----------------
// warp per edge position (b,i,j); lane = channel
__global__ __launch_bounds__(256) void edge_kernel(
    const float* __restrict__ edge,
    const float* __restrict__ eg, const float* __restrict__ eb,
    const float* __restrict__ Wke, const float* __restrict__ bke,
    const float* __restrict__ Web, const float* __restrict__ beb,
    float* __restrict__ kedge, float* __restrict__ biasout)
{
    __shared__ float sW[32 * 32];
    int tid = threadIdx.x;
    for (int i = tid; i < 1024; i += 256) sW[i] = Wke[i];
    __syncthreads();

    int lane = tid & 31;
    int w = tid >> 5;
    long long pos = (long long)blockIdx.x * 8 + w;
    float e = edge[pos * 32 + lane];

    float s = e;
    #pragma unroll
    for (int o = 16; o; o >>= 1) s += __shfl_xor_sync(0xffffffffu, s, o);
    float mean = s * (1.0f / 32.0f);
    float d = e - mean;
    float vq = d * d;
    #pragma unroll
    for (int o = 16; o; o >>= 1) vq += __shfl_xor_sync(0xffffffffu, vq, o);
    float inv = rsqrtf(vq * (1.0f / 32.0f) + 1e-5f);
    float ne = d * inv * eg[lane] + eb[lane];

    float pb = ne * Web[lane];
    #pragma unroll
    for (int o = 16; o; o >>= 1) pb += __shfl_xor_sync(0xffffffffu, pb, o);
    if (lane == 0) biasout[pos] = (pb + beb[0]) * 0.70710678118654752f;

    float acc = bke[lane];
    #pragma unroll
    for (int k = 0; k < 32; k++)
        acc += __shfl_sync(0xffffffffu, ne, k) * sW[k * 32 + lane];
    kedge[pos * 32 + lane] = acc;
}

// ---------------- generic tiled fp32 GEMM (64x64x16) ----------------
// C = act( alpha*A@B(^T) + bias + addend ) [+ C if accumulate]
__global__ __launch_bounds__(256) void gemm64_kernel(
    const float* __restrict__ A, const float* __restrict__ Bm, float* __restrict__ C,
    int M, int Nc, int K, int lda, int ldb, int ldc,
    int batch2,
    long long sA1, long long sA2, long long sB1, long long sB2,
    long long sC1, long long sC2,
    int transB, float alpha,
    const float* __restrict__ bias,
    const float* __restrict__ addend, int ldadd,
    int accumulate, int act_gelu)
{
    __shared__ float As[16][68];
    __shared__ float Bs[16][68];

    int z = blockIdx.z;
    int z1 = z / batch2, z2 = z % batch2;
    A  += z1 * sA1 + z2 * sA2;
    Bm += z1 * sB1 + z2 * sB2;
    C  += z1 * sC1 + z2 * sC2;

    int m0 = blockIdx.y * 64, n0 = blockIdx.x * 64;
    int tid = threadIdx.x;
    int tx = tid & 15, ty = tid >> 4;

    float acc[4][4] = {};

    int mmA = tid >> 2,  ksA = (tid & 3) * 4;   // A loader mapping
    int kkB = tid >> 4,  nnB = (tid & 15) * 4;  // B loader mapping (NN)
    int nnT = tid >> 2,  ksT = (tid & 3) * 4;   // B loader mapping (NT)

    for (int k0 = 0; k0 < K; k0 += 16) {
        float4 a = *(const float4*)&A[(size_t)(m0 + mmA) * lda + k0 + ksA];
        As[ksA + 0][mmA] = a.x; As[ksA + 1][mmA] = a.y;
        As[ksA + 2][mmA] = a.z; As[ksA + 3][mmA] = a.w;
        if (!transB) {
            float4 bv = *(const float4*)&Bm[(size_t)(k0 + kkB) * ldb + n0 + nnB];
            *(float4*)&Bs[kkB][nnB] = bv;
        } else {
            float4 bv = *(const float4*)&Bm[(size_t)(n0 + nnT) * ldb + k0 + ksT];
            Bs[ksT + 0][nnT] = bv.x; Bs[ksT + 1][nnT] = bv.y;
            Bs[ksT + 2][nnT] = bv.z; Bs[ksT + 3][nnT] = bv.w;
        }
        __syncthreads();
        #pragma unroll
        for (int kk = 0; kk < 16; kk++) {
            float4 ra = *(const float4*)&As[kk][ty * 4];
            float4 rb = *(const float4*)&Bs[kk][tx * 4];
            float av[4] = {ra.x, ra.y, ra.z, ra.w};
            float bv[4] = {rb.x, rb.y, rb.z, rb.w};
            #pragma unroll
            for (int i = 0; i < 4; i++)
                #pragma unroll
                for (int j = 0; j < 4; j++)
                    acc[i][j] += av[i] * bv[j];
        }
        __syncthreads();
    }

    #pragma unroll
    for (int i = 0; i < 4; i++) {
        int m = m0 + ty * 4 + i;
        size_t rowoff = (size_t)m * ldc;
        #pragma unroll
        for (int j = 0; j < 4; j++) {
            int n = n0 + tx * 4 + j;
            float v = acc[i][j] * alpha;
            if (bias)       v += bias[n];
            if (addend)     v += addend[(size_t)m * ldadd + n];
            if (accumulate) v += C[rowoff + n];
            if (act_gelu)   v = gelu_f(v);
            C[rowoff + n] = v;
        }
    }
}

// ---------------- softmax over 384 cols (adds edge bias + mask) ----------------
__global__ __launch_bounds__(128) void softmax_kernel(
    float* __restrict__ attn, const float* __restrict__ bias,
    const unsigned char* __restrict__ mask)
{
    __shared__ float sh[4];
    int row = blockIdx.x;               // (b*H + h)*N + i
    int b = row / (Ht * Nt);
    int i = row % Nt;
    float* sp = attn + (size_t)row * Nt;
    const float* bp = bias + ((size_t)b * Nt + i) * Nt;
    const unsigned char* mp = mask + ((size_t)b * Nt + i) * Nt;
    int t = threadIdx.x;

    float v[3];
    #pragma unroll
    for (int r = 0; r < 3; r++) {
        int j = t + r * 128;
        float s = sp[j] + bp[j];
        if (mp[j]) s = -INFINITY;
        v[r] = s;
    }
    float mx = fmaxf(fmaxf(v[0], v[1]), v[2]);
    mx = blockReduce128(mx, true, sh);
    __syncthreads();
    float sum = 0.0f;
    #pragma unroll
    for (int r = 0; r < 3; r++) { v[r] = __expf(v[r] - mx); sum += v[r]; }
    sum = blockReduce128(sum, false, sh);
    float invs = 1.0f / sum;
    #pragma unroll
    for (int r = 0; r < 3; r++) sp[t + r * 128] = v[r] * invs;
}

// ---------------- ectx: block per (b,i); attn staged in shared ----------------
__global__ __launch_bounds__(256) void ectx_kernel(
    const float* __restrict__ attn, const float* __restrict__ kedge,
    float* __restrict__ ectx)
{
    __shared__ float sA[Ht * Nt];       // 12 KB
    int bi = blockIdx.x;                // b*N + i
    int b = bi / Nt, i = bi % Nt;
    int t = threadIdx.x;
    for (int idx = t; idx < Ht * Nt; idx += 256) {
        int h = idx / Nt, j = idx % Nt;
        sA[idx] = attn[(((size_t)(b * Ht + h)) * Nt + i) * Nt + j];
    }
    __syncthreads();
    int h = t >> 5, de = t & 31;
    const float* kp = kedge + (size_t)bi * Nt * DEt + de;
    const float* ap = sA + h * Nt;
    float acc = 0.0f;
    #pragma unroll 4
    for (int j = 0; j < Nt; j++) acc += ap[j] * kp[(size_t)j * DEt];
    ectx[(size_t)bi * (Ht * DEt) + h * DEt + de] = acc;
}

// ---------------- launch ----------------
extern "C" void kernel_launch(void* const* d_in, const int* in_sizes, int n_in,
                              void* d_out, int out_size)
{
    const float* x      = (const float*)d_in[0];
    const float* edge   = (const float*)d_in[1];
    const unsigned char* mask = (const unsigned char*)d_in[2];
    const float* ln_a_g = (const float*)d_in[3];
    const float* ln_a_b = (const float*)d_in[4];
    const float* ln_e_g = (const float*)d_in[5];
    const float* ln_e_b = (const float*)d_in[6];
    const float* Wq = (const float*)d_in[7];   const float* bq = (const float*)d_in[8];
    const float* Wk = (const float*)d_in[9];   const float* bk = (const float*)d_in[10];
    const float* Wv = (const float*)d_in[11];  const float* bv = (const float*)d_in[12];
    const float* Wke = (const float*)d_in[13]; const float* bke = (const float*)d_in[14];
    const float* Web = (const float*)d_in[15]; const float* beb = (const float*)d_in[16];
    const float* Weo = (const float*)d_in[17]; const float* beo = (const float*)d_in[18];
    const float* Wo  = (const float*)d_in[19]; const float* bo  = (const float*)d_in[20];
    const float* ln_f_g = (const float*)d_in[21];
    const float* ln_f_b = (const float*)d_in[22];
    const float* W1 = (const float*)d_in[23];  const float* b1 = (const float*)d_in[24];
    const float* W2 = (const float*)d_in[25];  const float* b2 = (const float*)d_in[26];
    float* out = (float*)d_out;

    float* base;
    cudaGetSymbolAddress((void**)&base, g_scratch);
    float* nx    = base + OFF_NX;
    float* q     = base + OFF_Q;
    float* k     = base + OFF_K;
    float* v     = base + OFF_V;
    float* kedge = base + OFF_KEDGE;
    float* biasb = base + OFF_BIAS;
    float* attn  = base + OFF_ATTN;
    float* ctx   = base + OFF_CTX;
    float* ectx  = base + OFF_ECTX;
    float* ectxo = base + OFF_ECTXO;
    float* x1    = base + OFF_X1;
    float* nx2   = base + OFF_NX2;
    float* h1    = base + OFF_H1;

    // 1. LN(x)
    ln512_kernel<<<BN, 128>>>(x, ln_a_g, ln_a_b, nx);

    // 2. edge LN + Wke proj + bias
    edge_kernel<<<(Bt * NN) / 8, 256>>>(edge, ln_e_g, ln_e_b, Wke, bke, Web, beb,
                                        kedge, biasb);

    // 3-5. q, k, v projections: (3072,512) @ (512,512)
    dim3 gqkv(Dt / 64, BN / 64, 1);
    gemm64_kernel<<<gqkv, 256>>>(nx, Wq, q, BN, Dt, Dt, Dt, Dt, Dt,
        1, 0, 0, 0, 0, 0, 0, 0, 1.0f, bq, nullptr, 0, 0, 0);
    gemm64_kernel<<<gqkv, 256>>>(nx, Wk, k, BN, Dt, Dt, Dt, Dt, Dt,
        1, 0, 0, 0, 0, 0, 0, 0, 1.0f, bk, nullptr, 0, 0, 0);
    gemm64_kernel<<<gqkv, 256>>>(nx, Wv, v, BN, Dt, Dt, Dt, Dt, Dt,
        1, 0, 0, 0, 0, 0, 0, 0, 1.0f, bv, nullptr, 0, 0, 0);

    // 6. scores = alpha * Q @ K^T, batched over (b,h)
    dim3 gsc(Nt / 64, Nt / 64, Bt * Ht);
    gemm64_kernel<<<gsc, 256>>>(q, k, attn, Nt, Nt, DKt, Dt, Dt, Nt,
        Ht, (long long)Nt * Dt, 64, (long long)Nt * Dt, 64,
        (long long)Ht * NN, (long long)NN,
        1, 0.08838834764831845f, nullptr, nullptr, 0, 0, 0);

    // 7. softmax (+edge bias, +mask)
    softmax_kernel<<<Bt * Ht * Nt, 128>>>(attn, biasb, mask);

    // 8. ctx = attn @ V, batched over (b,h)
    dim3 gcx(DKt / 64, Nt / 64, Bt * Ht);
    gemm64_kernel<<<gcx, 256>>>(attn, v, ctx, Nt, DKt, Nt, Nt, Dt, Dt,
        Ht, (long long)Ht * NN, (long long)NN, (long long)Nt * Dt, 64,
        (long long)Nt * Dt, 64,
        0, 1.0f, nullptr, nullptr, 0, 0, 0);

    // 9. ectx = einsum(attn, kedge)
    ectx_kernel<<<BN, 256>>>(attn, kedge, ectx);

    // 10. ectxo = ectx @ Weo + beo : (3072,256)@(256,512)
    dim3 geo(Dt / 64, BN / 64, 1);
    gemm64_kernel<<<geo, 256>>>(ectx, Weo, ectxo, BN, Dt, Ht * DEt,
        Ht * DEt, Dt, Dt,
        1, 0, 0, 0, 0, 0, 0, 0, 1.0f, beo, nullptr, 0, 0, 0);

    // 11. x1 = x + ctx @ Wo_top + bo
    gemm64_kernel<<<geo, 256>>>(ctx, Wo, x1, BN, Dt, Dt, Dt, Dt, Dt,
        1, 0, 0, 0, 0, 0, 0, 0, 1.0f, bo, x, Dt, 0, 0);

    // 12. x1 += ectxo @ Wo_bot
    gemm64_kernel<<<geo, 256>>>(ectxo, Wo + (size_t)Dt * Dt, x1, BN, Dt, Dt,
        Dt, Dt, Dt,
        1, 0, 0, 0, 0, 0, 0, 0, 1.0f, nullptr, nullptr, 0, 1, 0);

    // 13. nx2 = LN(x1)
    ln512_kernel<<<BN, 128>>>(x1, ln_f_g, ln_f_b, nx2);

    // 14. h1 = gelu(nx2 @ W1 + b1) : (3072,512)@(512,2048)
    dim3 gf1(DFt / 64, BN / 64, 1);
    gemm64_kernel<<<gf1, 256>>>(nx2, W1, h1, BN, DFt, Dt, Dt, DFt, DFt,
        1, 0, 0, 0, 0, 0, 0, 0, 1.0f, b1, nullptr, 0, 0, 1);

    // 15. out = x1 + h1 @ W2 + b2 : (3072,2048)@(2048,512)
    dim3 gf2(Dt / 64, BN / 64, 1);
    gemm64_kernel<<<gf2, 256>>>(h1, W2, out, BN, Dt, DFt, DFt, Dt, Dt,
        1, 0, 0, 0, 0, 0, 0, 0, 1.0f, b2, x1, Dt, 0, 0);

    (void)in_sizes; (void)n_in; (void)out_size;
}

// round 3
// speedup vs baseline: 1.0787x; 1.0787x over previous
#include <cuda_runtime.h>
#include <cuda_bf16.h>
#include <math.h>
#include <stdint.h>

// ---------------- problem constants ----------------
#define Bt   8
#define Nt   384
#define Dt   512
#define Ht   8
#define DEt  32
#define DFt  2048
#define DKt  64
#define BNr  (Bt*Nt)            // 3072
#define NNt  (Nt*Nt)            // 147456

// scratch layout (floats)
#define OFF_NX     0LL
#define OFF_Q      (OFF_NX    + (long long)BNr*Dt)
#define OFF_K      (OFF_Q     + (long long)BNr*Dt)
#define OFF_V      (OFF_K     + (long long)BNr*Dt)
#define OFF_KEDGE  (OFF_V     + (long long)BNr*Dt)
#define OFF_BIAS   (OFF_KEDGE + (long long)Bt*NNt*DEt)
#define OFF_ATTN   (OFF_BIAS  + (long long)Bt*NNt)
#define OFF_CAT    (OFF_ATTN  + (long long)Bt*Ht*NNt)          // [BNr][1024] = [ctx | ectxo]
#define OFF_ECTX   (OFF_CAT   + (long long)BNr*2*Dt)
#define OFF_X1     (OFF_ECTX  + (long long)BNr*Ht*DEt)
#define OFF_NX2    (OFF_X1    + (long long)BNr*Dt)
#define OFF_H1     (OFF_NX2   + (long long)BNr*Dt)
#define SCRATCH_TOTAL (OFF_H1 + (long long)BNr*DFt)

static __device__ float g_scratch[SCRATCH_TOTAL];

// ---------------- helpers ----------------
__device__ __forceinline__ float gelu_f(float v) {
    float t3 = v * v * v;
    return 0.5f * v * (1.0f + tanhf(0.7978845608028654f * (v + 0.044715f * t3)));
}

__device__ __forceinline__ float f2tf(float x) {
    uint32_t u;
    asm("cvt.rna.tf32.f32 %0, %1;" : "=r"(u) : "f"(x));
    return __uint_as_float(u);
}

__device__ __forceinline__ void mma_tf32(float* c, const uint32_t* a, const uint32_t* b) {
    asm volatile(
        "mma.sync.aligned.m16n8k8.row.col.f32.tf32.tf32.f32 "
        "{%0,%1,%2,%3}, {%4,%5,%6,%7}, {%8,%9}, {%0,%1,%2,%3};\n"
        : "+f"(c[0]), "+f"(c[1]), "+f"(c[2]), "+f"(c[3])
        : "r"(a[0]), "r"(a[1]), "r"(a[2]), "r"(a[3]), "r"(b[0]), "r"(b[1]));
}

__device__ __forceinline__ float blockReduce128(float v, bool isMax, float* sh) {
    #pragma unroll
    for (int o = 16; o; o >>= 1) {
        float o2 = __shfl_xor_sync(0xffffffffu, v, o);
        v = isMax ? fmaxf(v, o2) : v + o2;
    }
    __syncthreads();
    if ((threadIdx.x & 31) == 0) sh[threadIdx.x >> 5] = v;
    __syncthreads();
    float r = sh[0];
    #pragma unroll
    for (int k = 1; k < 4; k++) r = isMax ? fmaxf(r, sh[k]) : r + sh[k];
    return r;
}

// ---------------- LayerNorm over 512 cols ----------------
__global__ __launch_bounds__(128) void ln512_kernel(
    const float* __restrict__ in, const float* __restrict__ g,
    const float* __restrict__ b, float* __restrict__ out)
{
    __shared__ float sh[4];
    int row = blockIdx.x;
    int t = threadIdx.x;
    const float4* inr = (const float4*)(in + (size_t)row * Dt);
    float4 v = inr[t];
    float s  = v.x + v.y + v.z + v.w;
    float sq = v.x*v.x + v.y*v.y + v.z*v.z + v.w*v.w;
    float tot = blockReduce128(s, false, sh);
    __syncthreads();
    float totq = blockReduce128(sq, false, sh);
    float mean = tot * (1.0f / Dt);
    float var  = totq * (1.0f / Dt) - mean * mean;
    float inv  = rsqrtf(var + 1e-5f);
    float4 gg = ((const float4*)g)[t];
    float4 bb = ((const float4*)b)[t];
    float4 o;
    o.x = (v.x - mean) * inv * gg.x + bb.x;
    o.y = (v.y - mean) * inv * gg.y + bb.y;
    o.z = (v.z - mean) * inv * gg.z + bb.z;
    o.w = (v.w - mean) * inv * gg.w + bb.w;
    ((float4*)(out + (size_t)row * Dt))[t] = o;
}

// ---------------- fused edge LN + Wke proj + scalar bias ----------------
__global__ __launch_bounds__(256) void edge_kernel(
    const float* __restrict__ edge,
    const float* __restrict__ eg, const float* __restrict__ eb,
    const float* __restrict__ Wke, const float* __restrict__ bke,
    const float* __restrict__ Web, const float* __restrict__ beb,
    float* __restrict__ kedge, float* __restrict__ biasout)
{
    __shared__ float sW[32 * 32];
    int tid = threadIdx.x;
    for (int i = tid; i < 1024; i += 256) sW[i] = Wke[i];
    __syncthreads();

    int lane = tid & 31;
    int w = tid >> 5;
    long long pos = (long long)blockIdx.x * 8 + w;
    float e = edge[pos * 32 + lane];

    float s = e;
    #pragma unroll
    for (int o = 16; o; o >>= 1) s += __shfl_xor_sync(0xffffffffu, s, o);
    float mean = s * (1.0f / 32.0f);
    float d = e - mean;
    float vq = d * d;
    #pragma unroll
    for (int o = 16; o; o >>= 1) vq += __shfl_xor_sync(0xffffffffu, vq, o);
    float inv = rsqrtf(vq * (1.0f / 32.0f) + 1e-5f);
    float ne = d * inv * eg[lane] + eb[lane];

    float pb = ne * Web[lane];
    #pragma unroll
    for (int o = 16; o; o >>= 1) pb += __shfl_xor_sync(0xffffffffu, pb, o);
    if (lane == 0) biasout[pos] = (pb + beb[0]) * 0.70710678118654752f;

    float acc = bke[lane];
    #pragma unroll
    for (int k = 0; k < 32; k++)
        acc += __shfl_sync(0xffffffffu, ne, k) * sW[k * 32 + lane];
    kedge[pos * 32 + lane] = acc;
}

// ---------------- tf32 tensor-core GEMM ----------------
// C = act( alpha*A@B(^T) + bias + addend ) [+ C if accumulate]
// TBM x TBN block tile, BK=32; 8 warps of WM x WN; fragments via padded SMEM.
template<int TBM, int TBN, int WM, int WN, bool TRANSB>
__global__ __launch_bounds__(256, 1) void gemm_tf32_kernel(
    const float* __restrict__ A, const float* __restrict__ Bm, float* __restrict__ C,
    int K, int lda, int ldb, int ldc,
    int batch2,
    long long sA1, long long sA2, long long sB1, long long sB2,
    long long sC1, long long sC2,
    float alpha, const float* __restrict__ bias,
    const float* __restrict__ addend, int ldadd,
    int accumulate, int act_gelu)
{
    constexpr int BK = 32;
    constexpr int WNC = TBN / WN;                 // warps along N
    constexpr int MF = WM / 16;
    constexpr int NF = WN / 8;
    constexpr int LDA_S = BK + 4;                 // 36 (m-major, k-minor)
    constexpr int LDB_S = TRANSB ? (BK + 4) : (TBN + 8);
    constexpr int BS_ROWS = TRANSB ? TBN : BK;
    constexpr int A_IT = TBM / 32;                // float4 loads per thread per stage
    constexpr int B_IT = TRANSB ? (TBN / 32) : ((BK * TBN) / 1024);

    extern __shared__ float smem[];
    float* As = smem;                             // [2][TBM][LDA_S]
    float* Bs = smem + 2 * TBM * LDA_S;           // [2][BS_ROWS][LDB_S]

    int z = blockIdx.z;
    int z1 = z / batch2, z2 = z % batch2;
    A  += z1 * sA1 + z2 * sA2;
    Bm += z1 * sB1 + z2 * sB2;
    C  += z1 * sC1 + z2 * sC2;

    const int m_blk = blockIdx.y * TBM;
    const int n_blk = blockIdx.x * TBN;

    const int tid = threadIdx.x;
    const int warp = tid >> 5, lane = tid & 31;
    const int g = lane >> 2, tig = lane & 3;
    const int wm = warp / WNC, wn = warp % WNC;
    const int m0 = wm * WM, n0 = wn * WN;

    float4 ra[A_IT], rb[B_IT];

    auto loadA = [&](int k0) {
        #pragma unroll
        for (int it = 0; it < A_IT; it++) {
            int idx = tid + it * 256;
            int r = idx >> 3, kq = (idx & 7) << 2;
            ra[it] = *(const float4*)&A[(size_t)(m_blk + r) * lda + k0 + kq];
        }
    };
    auto storeA = [&](int s) {
        #pragma unroll
        for (int it = 0; it < A_IT; it++) {
            int idx = tid + it * 256;
            int r = idx >> 3, kq = (idx & 7) << 2;
            float4 v = ra[it];
            v.x = f2tf(v.x); v.y = f2tf(v.y); v.z = f2tf(v.z); v.w = f2tf(v.w);
            *(float4*)&As[(s * TBM + r) * LDA_S + kq] = v;
        }
    };
    auto loadB = [&](int k0) {
        #pragma unroll
        for (int it = 0; it < B_IT; it++) {
            int idx = tid + it * 256;
            if (TRANSB) {
                int r = idx >> 3, kq = (idx & 7) << 2;
                rb[it] = *(const float4*)&Bm[(size_t)(n_blk + r) * ldb + k0 + kq];
            } else {
                int r = idx / (TBN / 4), c = (idx % (TBN / 4)) << 2;
                rb[it] = *(const float4*)&Bm[(size_t)(k0 + r) * ldb + n_blk + c];
            }
        }
    };
    auto storeB = [&](int s) {
        #pragma unroll
        for (int it = 0; it < B_IT; it++) {
            int idx = tid + it * 256;
            float4 v = rb[it];
            v.x = f2tf(v.x); v.y = f2tf(v.y); v.z = f2tf(v.z); v.w = f2tf(v.w);
            if (TRANSB) {
                int r = idx >> 3, kq = (idx & 7) << 2;
                *(float4*)&Bs[(s * BS_ROWS + r) * LDB_S + kq] = v;
            } else {
                int r = idx / (TBN / 4), c = (idx % (TBN / 4)) << 2;
                *(float4*)&Bs[(s * BS_ROWS + r) * LDB_S + c] = v;
            }
        }
    };

    float acc[MF][NF][4];
    #pragma unroll
    for (int i = 0; i < MF; i++)
        #pragma unroll
        for (int j = 0; j < NF; j++)
            #pragma unroll
            for (int q = 0; q < 4; q++) acc[i][j][q] = 0.0f;

    loadA(0); loadB(0);
    storeA(0); storeB(0);
    __syncthreads();

    const int nk = K / BK;
    for (int kt = 0; kt < nk; kt++) {
        int s = kt & 1;
        if (kt + 1 < nk) { loadA((kt + 1) * BK); loadB((kt + 1) * BK); }

        #pragma unroll
        for (int ks = 0; ks < 4; ks++) {
            int kb = ks * 8;
            uint32_t afr[MF][4], bfr[NF][2];
            #pragma unroll
            for (int i = 0; i < MF; i++) {
                const float* ap = &As[(s * TBM + m0 + i * 16) * LDA_S + kb];
                afr[i][0] = __float_as_uint(ap[(size_t)g * LDA_S + tig]);
                afr[i][1] = __float_as_uint(ap[(size_t)(g + 8) * LDA_S + tig]);
                afr[i][2] = __float_as_uint(ap[(size_t)g * LDA_S + tig + 4]);
                afr[i][3] = __float_as_uint(ap[(size_t)(g + 8) * LDA_S + tig + 4]);
            }
            #pragma unroll
            for (int j = 0; j < NF; j++) {
                if (TRANSB) {
                    const float* bp = &Bs[(s * BS_ROWS + n0 + j * 8 + g) * LDB_S + kb];
                    bfr[j][0] = __float_as_uint(bp[tig]);
                    bfr[j][1] = __float_as_uint(bp[tig + 4]);
                } else {
                    const float* bp = &Bs[(s * BS_ROWS + kb) * LDB_S + n0 + j * 8 + g];
                    bfr[j][0] = __float_as_uint(bp[(size_t)tig * LDB_S]);
                    bfr[j][1] = __float_as_uint(bp[(size_t)(tig + 4) * LDB_S]);
                }
            }
            #pragma unroll
            for (int i = 0; i < MF; i++)
                #pragma unroll
                for (int j = 0; j < NF; j++)
                    mma_tf32(acc[i][j], afr[i], bfr[j]);
        }

        if (kt + 1 < nk) { storeA(s ^ 1); storeB(s ^ 1); }
        __syncthreads();
    }

    // epilogue
    #pragma unroll
    for (int i = 0; i < MF; i++) {
        int row0 = m_blk + m0 + i * 16 + g;
        #pragma unroll
        for (int half = 0; half < 2; half++) {
            int row = row0 + half * 8;
            size_t roff = (size_t)row * ldc;
            #pragma unroll
            for (int j = 0; j < NF; j++) {
                int col = n_blk + n0 + j * 8 + tig * 2;
                float v0 = acc[i][j][half * 2 + 0] * alpha;
                float v1 = acc[i][j][half * 2 + 1] * alpha;
                if (bias)   { v0 += bias[col]; v1 += bias[col + 1]; }
                if (addend) {
                    const float* ad = &addend[(size_t)row * ldadd + col];
                    v0 += ad[0]; v1 += ad[1];
                }
                if (accumulate) { v0 += C[roff + col]; v1 += C[roff + col + 1]; }
                if (act_gelu)   { v0 = gelu_f(v0); v1 = gelu_f(v1); }
                float2 o = make_float2(v0, v1);
                *(float2*)&C[roff + col] = o;
            }
        }
    }
}

// ---------------- softmax over 384 cols (adds edge bias + mask) ----------------
__global__ __launch_bounds__(128) void softmax_kernel(
    float* __restrict__ attn, const float* __restrict__ bias,
    const unsigned char* __restrict__ mask)
{
    __shared__ float sh[4];
    int row = blockIdx.x;               // (b*H + h)*N + i
    int b = row / (Ht * Nt);
    int i = row % Nt;
    float* sp = attn + (size_t)row * Nt;
    const float* bp = bias + ((size_t)b * Nt + i) * Nt;
    const unsigned char* mp = mask + ((size_t)b * Nt + i) * Nt;
    int t = threadIdx.x;

    float v[3];
    #pragma unroll
    for (int r = 0; r < 3; r++) {
        int j = t + r * 128;
        float s = sp[j] + bp[j];
        if (mp[j]) s = -INFINITY;
        v[r] = s;
    }
    float mx = fmaxf(fmaxf(v[0], v[1]), v[2]);
    mx = blockReduce128(mx, true, sh);
    __syncthreads();
    float sum = 0.0f;
    #pragma unroll
    for (int r = 0; r < 3; r++) { v[r] = __expf(v[r] - mx); sum += v[r]; }
    sum = blockReduce128(sum, false, sh);
    float invs = 1.0f / sum;
    #pragma unroll
    for (int r = 0; r < 3; r++) sp[t + r * 128] = v[r] * invs;
}

// ---------------- ectx: block per (b,i); attn staged in shared ----------------
__global__ __launch_bounds__(256) void ectx_kernel(
    const float* __restrict__ attn, const float* __restrict__ kedge,
    float* __restrict__ ectx)
{
    __shared__ float sA[Ht * Nt];       // 12 KB
    int bi = blockIdx.x;                // b*N + i
    int b = bi / Nt, i = bi % Nt;
    int t = threadIdx.x;
    for (int idx = t; idx < Ht * Nt; idx += 256) {
        int h = idx / Nt, j = idx % Nt;
        sA[idx] = attn[(((size_t)(b * Ht + h)) * Nt + i) * Nt + j];
    }
    __syncthreads();
    int h = t >> 5, de = t & 31;
    const float* kp = kedge + (size_t)bi * Nt * DEt + de;
    const float* ap = sA + h * Nt;
    float acc = 0.0f;
    #pragma unroll 4
    for (int j = 0; j < Nt; j++) acc += ap[j] * kp[(size_t)j * DEt];
    ectx[(size_t)bi * (Ht * DEt) + h * DEt + de] = acc;
}

// ---------------- launch ----------------
extern "C" void kernel_launch(void* const* d_in, const int* in_sizes, int n_in,
                              void* d_out, int out_size)
{
    const float* x      = (const float*)d_in[0];
    const float* edge   = (const float*)d_in[1];
    const unsigned char* mask = (const unsigned char*)d_in[2];
    const float* ln_a_g = (const float*)d_in[3];
    const float* ln_a_b = (const float*)d_in[4];
    const float* ln_e_g = (const float*)d_in[5];
    const float* ln_e_b = (const float*)d_in[6];
    const float* Wq = (const float*)d_in[7];   const float* bq = (const float*)d_in[8];
    const float* Wk = (const float*)d_in[9];   const float* bk = (const float*)d_in[10];
    const float* Wv = (const float*)d_in[11];  const float* bv = (const float*)d_in[12];
    const float* Wke = (const float*)d_in[13]; const float* bke = (const float*)d_in[14];
    const float* Web = (const float*)d_in[15]; const float* beb = (const float*)d_in[16];
    const float* Weo = (const float*)d_in[17]; const float* beo = (const float*)d_in[18];
    const float* Wo  = (const float*)d_in[19]; const float* bo  = (const float*)d_in[20];
    const float* ln_f_g = (const float*)d_in[21];
    const float* ln_f_b = (const float*)d_in[22];
    const float* W1 = (const float*)d_in[23];  const float* b1 = (const float*)d_in[24];
    const float* W2 = (const float*)d_in[25];  const float* b2 = (const float*)d_in[26];
    float* out = (float*)d_out;

    float* base;
    cudaGetSymbolAddress((void**)&base, g_scratch);
    float* nx    = base + OFF_NX;
    float* q     = base + OFF_Q;
    float* k     = base + OFF_K;
    float* v     = base + OFF_V;
    float* kedge = base + OFF_KEDGE;
    float* biasb = base + OFF_BIAS;
    float* attn  = base + OFF_ATTN;
    float* cat   = base + OFF_CAT;       // [BNr][1024] = [ctx | ectxo]
    float* ectx  = base + OFF_ECTX;
    float* x1    = base + OFF_X1;
    float* nx2   = base + OFF_NX2;
    float* h1    = base + OFF_H1;

    // kernel instantiations
    auto GA = gemm_tf32_kernel<128, 128, 64, 32, false>;   // generic NN
    auto GT = gemm_tf32_kernel<128, 128, 64, 32, true>;    // NT (scores)
    auto GV = gemm_tf32_kernel<128, 64, 32, 32, false>;    // attn @ V

    constexpr int SMEM_GA = (2 * 128 * 36 + 2 * 32 * 136) * 4;   // 71680
    constexpr int SMEM_GT = (2 * 128 * 36 + 2 * 128 * 36) * 4;   // 73728
    constexpr int SMEM_GV = (2 * 128 * 36 + 2 * 32 * 72) * 4;    // 55296
    cudaFuncSetAttribute(GA, cudaFuncAttributeMaxDynamicSharedMemorySize, SMEM_GA);
    cudaFuncSetAttribute(GT, cudaFuncAttributeMaxDynamicSharedMemorySize, SMEM_GT);
    cudaFuncSetAttribute(GV, cudaFuncAttributeMaxDynamicSharedMemorySize, SMEM_GV);

    // 1. LN(x)
    ln512_kernel<<<BNr, 128>>>(x, ln_a_g, ln_a_b, nx);

    // 2. edge LN + Wke proj + bias
    edge_kernel<<<(Bt * NNt) / 8, 256>>>(edge, ln_e_g, ln_e_b, Wke, bke, Web, beb,
                                         kedge, biasb);

    // 3-5. q, k, v projections: (3072,512) @ (512,512)
    dim3 gqkv(Dt / 128, BNr / 128, 1);
    GA<<<gqkv, 256, SMEM_GA>>>(nx, Wq, q, Dt, Dt, Dt, Dt,
        1, 0, 0, 0, 0, 0, 0, 1.0f, bq, nullptr, 0, 0, 0);
    GA<<<gqkv, 256, SMEM_GA>>>(nx, Wk, k, Dt, Dt, Dt, Dt,
        1, 0, 0, 0, 0, 0, 0, 1.0f, bk, nullptr, 0, 0, 0);
    GA<<<gqkv, 256, SMEM_GA>>>(nx, Wv, v, Dt, Dt, Dt, Dt,
        1, 0, 0, 0, 0, 0, 0, 1.0f, bv, nullptr, 0, 0, 0);

    // 6. scores = alpha * Q @ K^T, batched over (b,h)
    dim3 gsc(Nt / 128, Nt / 128, Bt * Ht);
    GT<<<gsc, 256, SMEM_GT>>>(q, k, attn, DKt, Dt, Dt, Nt,
        Ht, (long long)Nt * Dt, 64, (long long)Nt * Dt, 64,
        (long long)Ht * NNt, (long long)NNt,
        0.08838834764831845f, nullptr, nullptr, 0, 0, 0);

    // 7. softmax (+edge bias, +mask)
    softmax_kernel<<<Bt * Ht * Nt, 128>>>(attn, biasb, mask);

    // 8. ctx half of cat = attn @ V, batched over (b,h); ldc=1024
    dim3 gcx(1, Nt / 128, Bt * Ht);
    GV<<<gcx, 256, SMEM_GV>>>(attn, v, cat, Nt, Nt, Dt, 2 * Dt,
        Ht, (long long)Ht * NNt, (long long)NNt, (long long)Nt * Dt, 64,
        (long long)Nt * 2 * Dt, 64,
        1.0f, nullptr, nullptr, 0, 0, 0);

    // 9. ectx = einsum(attn, kedge)
    ectx_kernel<<<BNr, 256>>>(attn, kedge, ectx);

    // 10. ectxo half of cat = ectx @ Weo + beo : (3072,256)@(256,512), ldc=1024
    dim3 geo(Dt / 128, BNr / 128, 1);
    GA<<<geo, 256, SMEM_GA>>>(ectx, Weo, cat + Dt, Ht * DEt, Ht * DEt, Dt, 2 * Dt,
        1, 0, 0, 0, 0, 0, 0, 1.0f, beo, nullptr, 0, 0, 0);

    // 11. x1 = x + cat @ Wo + bo : (3072,1024)@(1024,512)
    GA<<<geo, 256, SMEM_GA>>>(cat, Wo, x1, 2 * Dt, 2 * Dt, Dt, Dt,
        1, 0, 0, 0, 0, 0, 0, 1.0f, bo, x, Dt, 0, 0);

    // 12. nx2 = LN(x1)
    ln512_kernel<<<BNr, 128>>>(x1, ln_f_g, ln_f_b, nx2);

    // 13. h1 = gelu(nx2 @ W1 + b1) : (3072,512)@(512,2048)
    dim3 gf1(DFt / 128, BNr / 128, 1);
    GA<<<gf1, 256, SMEM_GA>>>(nx2, W1, h1, Dt, Dt, DFt, DFt,
        1, 0, 0, 0, 0, 0, 0, 1.0f, b1, nullptr, 0, 0, 1);

    // 14. out = x1 + h1 @ W2 + b2 : (3072,2048)@(2048,512)
    dim3 gf2(Dt / 128, BNr / 128, 1);
    GA<<<gf2, 256, SMEM_GA>>>(h1, W2, out, DFt, DFt, Dt, Dt,
        1, 0, 0, 0, 0, 0, 0, 1.0f, b2, x1, Dt, 0, 0);

    (void)in_sizes; (void)n_in; (void)out_size;
}

// round 4
// speedup vs baseline: 3.0941x; 2.8684x over previous
#include <cuda_runtime.h>
#include <cuda_bf16.h>
#include <math.h>
#include <stdint.h>

// ---------------- problem constants ----------------
#define Bt   8
#define Nt   384
#define Dt   512
#define Ht   8
#define DEt  32
#define DFt  2048
#define DKt  64
#define BNr  (Bt*Nt)            // 3072
#define NNt  (Nt*Nt)            // 147456
#define NPOS ((long long)Bt*NNt) // 1,179,648 edge positions

// scratch layout (floats)
#define OFF_NX     0LL
#define OFF_Q      (OFF_NX    + (long long)BNr*Dt)
#define OFF_K      (OFF_Q     + (long long)BNr*Dt)
#define OFF_V      (OFF_K     + (long long)BNr*Dt)
#define OFF_NE     (OFF_V     + (long long)BNr*Dt)
#define OFF_BIAS   (OFF_NE    + (long long)Bt*NNt*DEt)
#define OFF_ATTN   (OFF_BIAS  + (long long)Bt*NNt)
#define OFF_CAT    (OFF_ATTN  + (long long)Bt*Ht*NNt)          // [BNr][1024] = [ctx | ectxo]
#define OFF_RAW    (OFF_CAT   + (long long)BNr*2*Dt)
#define OFF_X1     (OFF_RAW   + (long long)BNr*Ht*DEt)
#define OFF_NX2    (OFF_X1    + (long long)BNr*Dt)
#define OFF_H1     (OFF_NX2   + (long long)BNr*Dt)
#define OFF_WFOLD  (OFF_H1    + (long long)BNr*DFt)
#define OFF_BFOLD  (OFF_WFOLD + (long long)Ht*DEt*Dt)
#define SCRATCH_TOTAL (OFF_BFOLD + Dt)

static __device__ float g_scratch[SCRATCH_TOTAL];

// ---------------- helpers ----------------
__device__ __forceinline__ float gelu_f(float v) {
    float t3 = v * v * v;
    return 0.5f * v * (1.0f + tanhf(0.7978845608028654f * (v + 0.044715f * t3)));
}

__device__ __forceinline__ float f2tf(float x) {
    uint32_t u;
    asm("cvt.rna.tf32.f32 %0, %1;" : "=r"(u) : "f"(x));
    return __uint_as_float(u);
}

__device__ __forceinline__ void mma_tf32(float* c, const uint32_t* a, const uint32_t* b) {
    asm volatile(
        "mma.sync.aligned.m16n8k8.row.col.f32.tf32.tf32.f32 "
        "{%0,%1,%2,%3}, {%4,%5,%6,%7}, {%8,%9}, {%0,%1,%2,%3};\n"
        : "+f"(c[0]), "+f"(c[1]), "+f"(c[2]), "+f"(c[3])
        : "r"(a[0]), "r"(a[1]), "r"(a[2]), "r"(a[3]), "r"(b[0]), "r"(b[1]));
}

__device__ __forceinline__ float blockReduce128(float v, bool isMax, float* sh) {
    #pragma unroll
    for (int o = 16; o; o >>= 1) {
        float o2 = __shfl_xor_sync(0xffffffffu, v, o);
        v = isMax ? fmaxf(v, o2) : v + o2;
    }
    __syncthreads();
    if ((threadIdx.x & 31) == 0) sh[threadIdx.x >> 5] = v;
    __syncthreads();
    float r = sh[0];
    #pragma unroll
    for (int k = 1; k < 4; k++) r = isMax ? fmaxf(r, sh[k]) : r + sh[k];
    return r;
}

// ---------------- LayerNorm over 512 cols ----------------
__global__ __launch_bounds__(128) void ln512_kernel(
    const float* __restrict__ in, const float* __restrict__ g,
    const float* __restrict__ b, float* __restrict__ out)
{
    __shared__ float sh[4];
    int row = blockIdx.x;
    int t = threadIdx.x;
    const float4* inr = (const float4*)(in + (size_t)row * Dt);
    float4 v = inr[t];
    float s  = v.x + v.y + v.z + v.w;
    float sq = v.x*v.x + v.y*v.y + v.z*v.z + v.w*v.w;
    float tot = blockReduce128(s, false, sh);
    __syncthreads();
    float totq = blockReduce128(sq, false, sh);
    float mean = tot * (1.0f / Dt);
    float var  = totq * (1.0f / Dt) - mean * mean;
    float inv  = rsqrtf(var + 1e-5f);
    float4 gg = ((const float4*)g)[t];
    float4 bb = ((const float4*)b)[t];
    float4 o;
    o.x = (v.x - mean) * inv * gg.x + bb.x;
    o.y = (v.y - mean) * inv * gg.y + bb.y;
    o.z = (v.z - mean) * inv * gg.z + bb.z;
    o.w = (v.w - mean) * inv * gg.w + bb.w;
    ((float4*)(out + (size_t)row * Dt))[t] = o;
}

// ---------------- edge LN + scalar bias (streaming; NO projection) ----------------
// warp handles 4 positions; 8 lanes per position, float4 per lane.
__global__ __launch_bounds__(256) void edge_ln_kernel(
    const float4* __restrict__ edge4,
    const float* __restrict__ eg, const float* __restrict__ eb,
    const float* __restrict__ Web, const float* __restrict__ beb,
    float4* __restrict__ ne4, float* __restrict__ biasout)
{
    int tid = threadIdx.x;
    int w = tid >> 5, lane = tid & 31;
    int p = lane >> 3, l8 = lane & 7;
    long long pos = (long long)blockIdx.x * 32 + w * 4 + p;

    float4 e = edge4[pos * 8 + l8];
    float s = e.x + e.y + e.z + e.w;
    s += __shfl_xor_sync(0xffffffffu, s, 4);
    s += __shfl_xor_sync(0xffffffffu, s, 2);
    s += __shfl_xor_sync(0xffffffffu, s, 1);
    float mean = s * (1.0f / 32.0f);
    float4 d = make_float4(e.x - mean, e.y - mean, e.z - mean, e.w - mean);
    float vq = d.x*d.x + d.y*d.y + d.z*d.z + d.w*d.w;
    vq += __shfl_xor_sync(0xffffffffu, vq, 4);
    vq += __shfl_xor_sync(0xffffffffu, vq, 2);
    vq += __shfl_xor_sync(0xffffffffu, vq, 1);
    float inv = rsqrtf(vq * (1.0f / 32.0f) + 1e-5f);

    float4 g4 = __ldg(&((const float4*)eg)[l8]);
    float4 b4 = __ldg(&((const float4*)eb)[l8]);
    float4 ne;
    ne.x = d.x * inv * g4.x + b4.x;
    ne.y = d.y * inv * g4.y + b4.y;
    ne.z = d.z * inv * g4.z + b4.z;
    ne.w = d.w * inv * g4.w + b4.w;

    float4 wb = __ldg(&((const float4*)Web)[l8]);
    float pb = ne.x*wb.x + ne.y*wb.y + ne.z*wb.z + ne.w*wb.w;
    pb += __shfl_xor_sync(0xffffffffu, pb, 4);
    pb += __shfl_xor_sync(0xffffffffu, pb, 2);
    pb += __shfl_xor_sync(0xffffffffu, pb, 1);
    if (l8 == 0) biasout[pos] = (pb + __ldg(beb)) * 0.70710678118654752f;

    ne4[pos * 8 + l8] = ne;
}

// ---------------- fold kernels: Wfold = Wke @ Weo_h ; biasfold ----------------
__global__ __launch_bounds__(128) void fold_w_kernel(
    const float* __restrict__ Wke, const float* __restrict__ Weo,
    float* __restrict__ Wfold)
{
    __shared__ float sK[32 * 32];
    int t = threadIdx.x;
    for (int i = t; i < 1024; i += 128) sK[i] = Wke[i];
    __syncthreads();
    int h = blockIdx.x;
    int d = blockIdx.y * 128 + t;
    float wcol[32];
    #pragma unroll
    for (int c = 0; c < 32; c++)
        wcol[c] = Weo[(size_t)(h * 32 + c) * Dt + d];
    for (int k = 0; k < 32; k++) {
        float acc = 0.0f;
        #pragma unroll
        for (int c = 0; c < 32; c++) acc += sK[k * 32 + c] * wcol[c];
        Wfold[(size_t)(h * 32 + k) * Dt + d] = acc;
    }
}

__global__ __launch_bounds__(128) void fold_b_kernel(
    const float* __restrict__ bke, const float* __restrict__ Weo,
    const float* __restrict__ beo, float* __restrict__ biasfold)
{
    int d = blockIdx.x * 128 + threadIdx.x;
    float acc = beo[d];
    for (int h = 0; h < Ht; h++)
        #pragma unroll
        for (int c = 0; c < 32; c++)
            acc += bke[c] * Weo[(size_t)(h * 32 + c) * Dt + d];
    biasfold[d] = acc;
}

// ---------------- tf32 tensor-core GEMM ----------------
template<int TBM, int TBN, int WM, int WN, bool TRANSB>
__global__ __launch_bounds__(256, 1) void gemm_tf32_kernel(
    const float* __restrict__ A, const float* __restrict__ Bm, float* __restrict__ C,
    int K, int lda, int ldb, int ldc,
    int batch2,
    long long sA1, long long sA2, long long sB1, long long sB2,
    long long sC1, long long sC2,
    float alpha, const float* __restrict__ bias,
    const float* __restrict__ addend, int ldadd,
    int accumulate, int act_gelu)
{
    constexpr int BK = 32;
    constexpr int WNC = TBN / WN;
    constexpr int MF = WM / 16;
    constexpr int NF = WN / 8;
    constexpr int LDA_S = BK + 4;
    constexpr int LDB_S = TRANSB ? (BK + 4) : (TBN + 8);
    constexpr int BS_ROWS = TRANSB ? TBN : BK;
    constexpr int A_IT = TBM / 32;
    constexpr int B_IT = TRANSB ? (TBN / 32) : ((BK * TBN) / 1024);

    extern __shared__ float smem[];
    float* As = smem;
    float* Bs = smem + 2 * TBM * LDA_S;

    int z = blockIdx.z;
    int z1 = z / batch2, z2 = z % batch2;
    A  += z1 * sA1 + z2 * sA2;
    Bm += z1 * sB1 + z2 * sB2;
    C  += z1 * sC1 + z2 * sC2;

    const int m_blk = blockIdx.y * TBM;
    const int n_blk = blockIdx.x * TBN;

    const int tid = threadIdx.x;
    const int warp = tid >> 5, lane = tid & 31;
    const int g = lane >> 2, tig = lane & 3;
    const int wm = warp / WNC, wn = warp % WNC;
    const int m0 = wm * WM, n0 = wn * WN;

    float4 ra[A_IT], rb[B_IT];

    auto loadA = [&](int k0) {
        #pragma unroll
        for (int it = 0; it < A_IT; it++) {
            int idx = tid + it * 256;
            int r = idx >> 3, kq = (idx & 7) << 2;
            ra[it] = *(const float4*)&A[(size_t)(m_blk + r) * lda + k0 + kq];
        }
    };
    auto storeA = [&](int s) {
        #pragma unroll
        for (int it = 0; it < A_IT; it++) {
            int idx = tid + it * 256;
            int r = idx >> 3, kq = (idx & 7) << 2;
            float4 v = ra[it];
            v.x = f2tf(v.x); v.y = f2tf(v.y); v.z = f2tf(v.z); v.w = f2tf(v.w);
            *(float4*)&As[(s * TBM + r) * LDA_S + kq] = v;
        }
    };
    auto loadB = [&](int k0) {
        #pragma unroll
        for (int it = 0; it < B_IT; it++) {
            int idx = tid + it * 256;
            if (TRANSB) {
                int r = idx >> 3, kq = (idx & 7) << 2;
                rb[it] = *(const float4*)&Bm[(size_t)(n_blk + r) * ldb + k0 + kq];
            } else {
                int r = idx / (TBN / 4), c = (idx % (TBN / 4)) << 2;
                rb[it] = *(const float4*)&Bm[(size_t)(k0 + r) * ldb + n_blk + c];
            }
        }
    };
    auto storeB = [&](int s) {
        #pragma unroll
        for (int it = 0; it < B_IT; it++) {
            int idx = tid + it * 256;
            float4 v = rb[it];
            v.x = f2tf(v.x); v.y = f2tf(v.y); v.z = f2tf(v.z); v.w = f2tf(v.w);
            if (TRANSB) {
                int r = idx >> 3, kq = (idx & 7) << 2;
                *(float4*)&Bs[(s * BS_ROWS + r) * LDB_S + kq] = v;
            } else {
                int r = idx / (TBN / 4), c = (idx % (TBN / 4)) << 2;
                *(float4*)&Bs[(s * BS_ROWS + r) * LDB_S + c] = v;
            }
        }
    };

    float acc[MF][NF][4];
    #pragma unroll
    for (int i = 0; i < MF; i++)
        #pragma unroll
        for (int j = 0; j < NF; j++)
            #pragma unroll
            for (int q = 0; q < 4; q++) acc[i][j][q] = 0.0f;

    loadA(0); loadB(0);
    storeA(0); storeB(0);
    __syncthreads();

    const int nk = K / BK;
    for (int kt = 0; kt < nk; kt++) {
        int s = kt & 1;
        if (kt + 1 < nk) { loadA((kt + 1) * BK); loadB((kt + 1) * BK); }

        #pragma unroll
        for (int ks = 0; ks < 4; ks++) {
            int kb = ks * 8;
            uint32_t afr[MF][4], bfr[NF][2];
            #pragma unroll
            for (int i = 0; i < MF; i++) {
                const float* ap = &As[(s * TBM + m0 + i * 16) * LDA_S + kb];
                afr[i][0] = __float_as_uint(ap[(size_t)g * LDA_S + tig]);
                afr[i][1] = __float_as_uint(ap[(size_t)(g + 8) * LDA_S + tig]);
                afr[i][2] = __float_as_uint(ap[(size_t)g * LDA_S + tig + 4]);
                afr[i][3] = __float_as_uint(ap[(size_t)(g + 8) * LDA_S + tig + 4]);
            }
            #pragma unroll
            for (int j = 0; j < NF; j++) {
                if (TRANSB) {
                    const float* bp = &Bs[(s * BS_ROWS + n0 + j * 8 + g) * LDB_S + kb];
                    bfr[j][0] = __float_as_uint(bp[tig]);
                    bfr[j][1] = __float_as_uint(bp[tig + 4]);
                } else {
                    const float* bp = &Bs[(s * BS_ROWS + kb) * LDB_S + n0 + j * 8 + g];
                    bfr[j][0] = __float_as_uint(bp[(size_t)tig * LDB_S]);
                    bfr[j][1] = __float_as_uint(bp[(size_t)(tig + 4) * LDB_S]);
                }
            }
            #pragma unroll
            for (int i = 0; i < MF; i++)
                #pragma unroll
                for (int j = 0; j < NF; j++)
                    mma_tf32(acc[i][j], afr[i], bfr[j]);
        }

        if (kt + 1 < nk) { storeA(s ^ 1); storeB(s ^ 1); }
        __syncthreads();
    }

    #pragma unroll
    for (int i = 0; i < MF; i++) {
        int row0 = m_blk + m0 + i * 16 + g;
        #pragma unroll
        for (int half = 0; half < 2; half++) {
            int row = row0 + half * 8;
            size_t roff = (size_t)row * ldc;
            #pragma unroll
            for (int j = 0; j < NF; j++) {
                int col = n_blk + n0 + j * 8 + tig * 2;
                float v0 = acc[i][j][half * 2 + 0] * alpha;
                float v1 = acc[i][j][half * 2 + 1] * alpha;
                if (bias)   { v0 += bias[col]; v1 += bias[col + 1]; }
                if (addend) {
                    const float* ad = &addend[(size_t)row * ldadd + col];
                    v0 += ad[0]; v1 += ad[1];
                }
                if (accumulate) { v0 += C[roff + col]; v1 += C[roff + col + 1]; }
                if (act_gelu)   { v0 = gelu_f(v0); v1 = gelu_f(v1); }
                float2 o = make_float2(v0, v1);
                *(float2*)&C[roff + col] = o;
            }
        }
    }
}

// ---------------- softmax over 384 cols (adds edge bias + mask) ----------------
__global__ __launch_bounds__(128) void softmax_kernel(
    float* __restrict__ attn, const float* __restrict__ bias,
    const unsigned char* __restrict__ mask)
{
    __shared__ float sh[4];
    int row = blockIdx.x;               // (b*H + h)*N + i
    int b = row / (Ht * Nt);
    int i = row % Nt;
    float* sp = attn + (size_t)row * Nt;
    const float* bp = bias + ((size_t)b * Nt + i) * Nt;
    const unsigned char* mp = mask + ((size_t)b * Nt + i) * Nt;
    int t = threadIdx.x;

    float v[3];
    #pragma unroll
    for (int r = 0; r < 3; r++) {
        int j = t + r * 128;
        float s = sp[j] + bp[j];
        if (mp[j]) s = -INFINITY;
        v[r] = s;
    }
    float mx = fmaxf(fmaxf(v[0], v[1]), v[2]);
    mx = blockReduce128(mx, true, sh);
    __syncthreads();
    float sum = 0.0f;
    #pragma unroll
    for (int r = 0; r < 3; r++) { v[r] = __expf(v[r] - mx); sum += v[r]; }
    sum = blockReduce128(sum, false, sh);
    float invs = 1.0f / sum;
    #pragma unroll
    for (int r = 0; r < 3; r++) sp[t + r * 128] = v[r] * invs;
}

// ---------------- ectx_raw: tensor-core contraction attn x ne ----------------
// block = (b,i), 128 threads / 4 warps. raw[bi][h*32+c] = sum_j attn[b,h,i,j]*ne[b,i,j,c]
__global__ __launch_bounds__(128) void ectx_raw_kernel(
    const float* __restrict__ attn, const float* __restrict__ ne,
    float* __restrict__ raw)
{
    constexpr int LDAS = 388;          // [16][388] (rows 8..15 garbage, outputs discarded)
    constexpr int LDBS = 40;           // [128][40]
    __shared__ float sA[16 * LDAS];    // 24832 B
    __shared__ float sB[128 * LDBS];   // 20480 B

    int bi = blockIdx.x;               // b*N + i
    int b = bi / Nt, i = bi % Nt;
    int t = threadIdx.x;
    int warp = t >> 5, lane = t & 31;
    int g = lane >> 2, tig = lane & 3;
    int n0 = warp * 8;

    // stage attn rows (8 x 384), tf32-rounded
    #pragma unroll
    for (int it = 0; it < 24; it++) {
        int idx = t + it * 128;
        int h = idx / Nt, j = idx % Nt;
        sA[h * LDAS + j] = f2tf(attn[(((size_t)(b * Ht + h)) * Nt + i) * Nt + j]);
    }

    float acc[4] = {0.0f, 0.0f, 0.0f, 0.0f};
    const float4* nep = (const float4*)ne + (size_t)bi * Nt * 8;

    for (int ch = 0; ch < 3; ch++) {
        __syncthreads();
        // stage ne chunk: 128 j-rows x 32 ch
        #pragma unroll
        for (int it = 0; it < 8; it++) {
            int idx = t + it * 128;
            int jr = idx >> 3, q = idx & 7;
            float4 v = nep[(size_t)(ch * 128 + jr) * 8 + q];
            v.x = f2tf(v.x); v.y = f2tf(v.y); v.z = f2tf(v.z); v.w = f2tf(v.w);
            *(float4*)&sB[jr * LDBS + q * 4] = v;
        }
        __syncthreads();

        #pragma unroll
        for (int k8 = 0; k8 < 16; k8++) {
            int kb = k8 * 8;
            int kg = ch * 128 + kb;
            uint32_t afr[4], bfr[2];
            afr[0] = __float_as_uint(sA[g * LDAS + kg + tig]);
            afr[1] = __float_as_uint(sA[(g + 8) * LDAS + kg + tig]);
            afr[2] = __float_as_uint(sA[g * LDAS + kg + tig + 4]);
            afr[3] = __float_as_uint(sA[(g + 8) * LDAS + kg + tig + 4]);
            bfr[0] = __float_as_uint(sB[(kb + tig) * LDBS + n0 + g]);
            bfr[1] = __float_as_uint(sB[(kb + tig + 4) * LDBS + n0 + g]);
            mma_tf32(acc, afr, bfr);
        }
    }

    // rows 0..7 valid (g = h); c0,c1 -> (row g, cols tig*2, tig*2+1)
    float2 o = make_float2(acc[0], acc[1]);
    *(float2*)&raw[(size_t)bi * (Ht * DEt) + g * DEt + n0 + tig * 2] = o;
}

// ---------------- launch ----------------
extern "C" void kernel_launch(void* const* d_in, const int* in_sizes, int n_in,
                              void* d_out, int out_size)
{
    const float* x      = (const float*)d_in[0];
    const float* edge   = (const float*)d_in[1];
    const unsigned char* mask = (const unsigned char*)d_in[2];
    const float* ln_a_g = (const float*)d_in[3];
    const float* ln_a_b = (const float*)d_in[4];
    const float* ln_e_g = (const float*)d_in[5];
    const float* ln_e_b = (const float*)d_in[6];
    const float* Wq = (const float*)d_in[7];   const float* bq = (const float*)d_in[8];
    const float* Wk = (const float*)d_in[9];   const float* bk = (const float*)d_in[10];
    const float* Wv = (const float*)d_in[11];  const float* bv = (const float*)d_in[12];
    const float* Wke = (const float*)d_in[13]; const float* bke = (const float*)d_in[14];
    const float* Web = (const float*)d_in[15]; const float* beb = (const float*)d_in[16];
    const float* Weo = (const float*)d_in[17]; const float* beo = (const float*)d_in[18];
    const float* Wo  = (const float*)d_in[19]; const float* bo  = (const float*)d_in[20];
    const float* ln_f_g = (const float*)d_in[21];
    const float* ln_f_b = (const float*)d_in[22];
    const float* W1 = (const float*)d_in[23];  const float* b1 = (const float*)d_in[24];
    const float* W2 = (const float*)d_in[25];  const float* b2 = (const float*)d_in[26];
    float* out = (float*)d_out;

    float* base;
    cudaGetSymbolAddress((void**)&base, g_scratch);
    float* nx    = base + OFF_NX;
    float* q     = base + OFF_Q;
    float* k     = base + OFF_K;
    float* v     = base + OFF_V;
    float* ne    = base + OFF_NE;
    float* biasb = base + OFF_BIAS;
    float* attn  = base + OFF_ATTN;
    float* cat   = base + OFF_CAT;       // [BNr][1024] = [ctx | ectxo]
    float* raw   = base + OFF_RAW;
    float* x1    = base + OFF_X1;
    float* nx2   = base + OFF_NX2;
    float* h1    = base + OFF_H1;
    float* Wfold = base + OFF_WFOLD;
    float* bfold = base + OFF_BFOLD;

    auto GA = gemm_tf32_kernel<128, 128, 64, 32, false>;   // generic NN
    auto GT = gemm_tf32_kernel<128, 128, 64, 32, true>;    // NT (scores)
    auto GV = gemm_tf32_kernel<128, 64, 32, 32, false>;    // attn @ V

    constexpr int SMEM_GA = (2 * 128 * 36 + 2 * 32 * 136) * 4;   // 71680
    constexpr int SMEM_GT = (2 * 128 * 36 + 2 * 128 * 36) * 4;   // 73728
    constexpr int SMEM_GV = (2 * 128 * 36 + 2 * 32 * 72) * 4;    // 55296
    cudaFuncSetAttribute(GA, cudaFuncAttributeMaxDynamicSharedMemorySize, SMEM_GA);
    cudaFuncSetAttribute(GT, cudaFuncAttributeMaxDynamicSharedMemorySize, SMEM_GT);
    cudaFuncSetAttribute(GV, cudaFuncAttributeMaxDynamicSharedMemorySize, SMEM_GV);

    // 0. fold Wke/bke into Weo (tiny)
    fold_w_kernel<<<dim3(Ht, Dt / 128), 128>>>(Wke, Weo, Wfold);
    fold_b_kernel<<<Dt / 128, 128>>>(bke, Weo, beo, bfold);

    // 1. LN(x)
    ln512_kernel<<<BNr, 128>>>(x, ln_a_g, ln_a_b, nx);

    // 2. edge LN + scalar bias (streaming)
    edge_ln_kernel<<<(int)(NPOS / 32), 256>>>((const float4*)edge, ln_e_g, ln_e_b,
                                              Web, beb, (float4*)ne, biasb);

    // 3-5. q, k, v projections
    dim3 gqkv(Dt / 128, BNr / 128, 1);
    GA<<<gqkv, 256, SMEM_GA>>>(nx, Wq, q, Dt, Dt, Dt, Dt,
        1, 0, 0, 0, 0, 0, 0, 1.0f, bq, nullptr, 0, 0, 0);
    GA<<<gqkv, 256, SMEM_GA>>>(nx, Wk, k, Dt, Dt, Dt, Dt,
        1, 0, 0, 0, 0, 0, 0, 1.0f, bk, nullptr, 0, 0, 0);
    GA<<<gqkv, 256, SMEM_GA>>>(nx, Wv, v, Dt, Dt, Dt, Dt,
        1, 0, 0, 0, 0, 0, 0, 1.0f, bv, nullptr, 0, 0, 0);

    // 6. scores = alpha * Q @ K^T, batched over (b,h)
    dim3 gsc(Nt / 128, Nt / 128, Bt * Ht);
    GT<<<gsc, 256, SMEM_GT>>>(q, k, attn, DKt, Dt, Dt, Nt,
        Ht, (long long)Nt * Dt, 64, (long long)Nt * Dt, 64,
        (long long)Ht * NNt, (long long)NNt,
        0.08838834764831845f, nullptr, nullptr, 0, 0, 0);

    // 7. softmax (+edge bias, +mask)
    softmax_kernel<<<Bt * Ht * Nt, 128>>>(attn, biasb, mask);

    // 8. ctx half of cat = attn @ V
    dim3 gcx(1, Nt / 128, Bt * Ht);
    GV<<<gcx, 256, SMEM_GV>>>(attn, v, cat, Nt, Nt, Dt, 2 * Dt,
        Ht, (long long)Ht * NNt, (long long)NNt, (long long)Nt * Dt, 64,
        (long long)Nt * 2 * Dt, 64,
        1.0f, nullptr, nullptr, 0, 0, 0);

    // 9. raw = attn x ne contraction (tensor cores)
    ectx_raw_kernel<<<BNr, 128>>>(attn, ne, raw);

    // 10. ectxo half of cat = raw @ Wfold + biasfold
    dim3 geo(Dt / 128, BNr / 128, 1);
    GA<<<geo, 256, SMEM_GA>>>(raw, Wfold, cat + Dt, Ht * DEt, Ht * DEt, Dt, 2 * Dt,
        1, 0, 0, 0, 0, 0, 0, 1.0f, bfold, nullptr, 0, 0, 0);

    // 11. x1 = x + cat @ Wo + bo
    GA<<<geo, 256, SMEM_GA>>>(cat, Wo, x1, 2 * Dt, 2 * Dt, Dt, Dt,
        1, 0, 0, 0, 0, 0, 0, 1.0f, bo, x, Dt, 0, 0);

    // 12. nx2 = LN(x1)
    ln512_kernel<<<BNr, 128>>>(x1, ln_f_g, ln_f_b, nx2);

    // 13. h1 = gelu(nx2 @ W1 + b1)
    dim3 gf1(DFt / 128, BNr / 128, 1);
    GA<<<gf1, 256, SMEM_GA>>>(nx2, W1, h1, Dt, Dt, DFt, DFt,
        1, 0, 0, 0, 0, 0, 0, 1.0f, b1, nullptr, 0, 0, 1);

    // 14. out = x1 + h1 @ W2 + b2
    dim3 gf2(Dt / 128, BNr / 128, 1);
    GA<<<gf2, 256, SMEM_GA>>>(h1, W2, out, DFt, DFt, Dt, Dt,
        1, 0, 0, 0, 0, 0, 0, 1.0f, b2, x1, Dt, 0, 0);

    (void)in_sizes; (void)n_in; (void)out_size;
}

// round 5
// speedup vs baseline: 3.1200x; 1.0084x over previous
#include <cuda_runtime.h>
#include <cuda_bf16.h>
#include <math.h>
#include <stdint.h>

// ---------------- problem constants ----------------
#define Bt   8
#define Nt   384
#define Dt   512
#define Ht   8
#define DEt  32
#define DFt  2048
#define DKt  64
#define BNr  (Bt*Nt)            // 3072
#define NNt  (Nt*Nt)            // 147456

// scratch layout (floats)
#define OFF_NX     0LL
#define OFF_QKV    (OFF_NX    + (long long)BNr*Dt)
#define OFF_ATTN   (OFF_QKV   + (long long)BNr*3*Dt)
#define OFF_CAT    (OFF_ATTN  + (long long)Bt*Ht*NNt)   // [BNr][768] = [ctx | raw]
#define OFF_X1     (OFF_CAT   + (long long)BNr*768)
#define OFF_NX2    (OFF_X1    + (long long)BNr*Dt)
#define OFF_H1     (OFF_NX2   + (long long)BNr*Dt)
#define OFF_WQKV   (OFF_H1    + (long long)BNr*DFt)
#define OFF_BQKV   (OFF_WQKV  + (long long)Dt*3*Dt)
#define OFF_WFOLD  (OFF_BQKV  + 3*Dt)
#define OFF_BFOLD  (OFF_WFOLD + (long long)Ht*DEt*Dt)
#define OFF_WCAT   (OFF_BFOLD + Dt)                      // [768][512]
#define OFF_BCOMB  (OFF_WCAT  + (long long)768*Dt)
#define SCRATCH_TOTAL (OFF_BCOMB + Dt)

static __device__ float g_scratch[SCRATCH_TOTAL];

// ---------------- helpers ----------------
__device__ __forceinline__ float gelu_f(float v) {
    float t3 = v * v * v;
    return 0.5f * v * (1.0f + tanhf(0.7978845608028654f * (v + 0.044715f * t3)));
}

__device__ __forceinline__ float f2tf(float x) {
    uint32_t u;
    asm("cvt.rna.tf32.f32 %0, %1;" : "=r"(u) : "f"(x));
    return __uint_as_float(u);
}

__device__ __forceinline__ void mma_tf32(float* c, const uint32_t* a, const uint32_t* b) {
    asm volatile(
        "mma.sync.aligned.m16n8k8.row.col.f32.tf32.tf32.f32 "
        "{%0,%1,%2,%3}, {%4,%5,%6,%7}, {%8,%9}, {%0,%1,%2,%3};\n"
        : "+f"(c[0]), "+f"(c[1]), "+f"(c[2]), "+f"(c[3])
        : "r"(a[0]), "r"(a[1]), "r"(a[2]), "r"(a[3]), "r"(b[0]), "r"(b[1]));
}

__device__ __forceinline__ float blockReduce128(float v, bool isMax, float* sh) {
    #pragma unroll
    for (int o = 16; o; o >>= 1) {
        float o2 = __shfl_xor_sync(0xffffffffu, v, o);
        v = isMax ? fmaxf(v, o2) : v + o2;
    }
    __syncthreads();
    if ((threadIdx.x & 31) == 0) sh[threadIdx.x >> 5] = v;
    __syncthreads();
    float r = sh[0];
    #pragma unroll
    for (int k = 1; k < 4; k++) r = isMax ? fmaxf(r, sh[k]) : r + sh[k];
    return r;
}

// ---------------- LayerNorm over 512 cols ----------------
__global__ __launch_bounds__(128) void ln512_kernel(
    const float* __restrict__ in, const float* __restrict__ g,
    const float* __restrict__ b, float* __restrict__ out)
{
    __shared__ float sh[4];
    int row = blockIdx.x;
    int t = threadIdx.x;
    const float4* inr = (const float4*)(in + (size_t)row * Dt);
    float4 v = inr[t];
    float s  = v.x + v.y + v.z + v.w;
    float sq = v.x*v.x + v.y*v.y + v.z*v.z + v.w*v.w;
    float tot = blockReduce128(s, false, sh);
    __syncthreads();
    float totq = blockReduce128(sq, false, sh);
    float mean = tot * (1.0f / Dt);
    float var  = totq * (1.0f / Dt) - mean * mean;
    float inv  = rsqrtf(var + 1e-5f);
    float4 gg = ((const float4*)g)[t];
    float4 bb = ((const float4*)b)[t];
    float4 o;
    o.x = (v.x - mean) * inv * gg.x + bb.x;
    o.y = (v.y - mean) * inv * gg.y + bb.y;
    o.z = (v.z - mean) * inv * gg.z + bb.z;
    o.w = (v.w - mean) * inv * gg.w + bb.w;
    ((float4*)(out + (size_t)row * Dt))[t] = o;
}

// ---------------- pack: Wqkv, bqkv, Wcat(top=Wo_top) ----------------
__global__ __launch_bounds__(256) void pack_kernel(
    const float* __restrict__ Wq, const float* __restrict__ Wk,
    const float* __restrict__ Wv,
    const float* __restrict__ bq, const float* __restrict__ bk,
    const float* __restrict__ bv,
    const float* __restrict__ Wo,
    float* __restrict__ Wqkv, float* __restrict__ bqkv, float* __restrict__ Wcat)
{
    int k = blockIdx.x;
    for (int n = threadIdx.x; n < Dt; n += 256) {
        Wqkv[(size_t)k * 1536 + n]        = Wq[(size_t)k * Dt + n];
        Wqkv[(size_t)k * 1536 + 512 + n]  = Wk[(size_t)k * Dt + n];
        Wqkv[(size_t)k * 1536 + 1024 + n] = Wv[(size_t)k * Dt + n];
        Wcat[(size_t)k * Dt + n]          = Wo[(size_t)k * Dt + n];
    }
    if (k == 0) {
        for (int n = threadIdx.x; n < Dt; n += 256) {
            bqkv[n] = bq[n]; bqkv[512 + n] = bk[n]; bqkv[1024 + n] = bv[n];
        }
    }
}

// ---------------- fold kernels ----------------
__global__ __launch_bounds__(128) void fold_w_kernel(
    const float* __restrict__ Wke, const float* __restrict__ Weo,
    float* __restrict__ Wfold)
{
    __shared__ float sK[32 * 32];
    int t = threadIdx.x;
    for (int i = t; i < 1024; i += 128) sK[i] = Wke[i];
    __syncthreads();
    int h = blockIdx.x;
    int d = blockIdx.y * 128 + t;
    float wcol[32];
    #pragma unroll
    for (int c = 0; c < 32; c++)
        wcol[c] = Weo[(size_t)(h * 32 + c) * Dt + d];
    for (int k = 0; k < 32; k++) {
        float acc = 0.0f;
        #pragma unroll
        for (int c = 0; c < 32; c++) acc += sK[k * 32 + c] * wcol[c];
        Wfold[(size_t)(h * 32 + k) * Dt + d] = acc;
    }
}

__global__ __launch_bounds__(128) void fold_b_kernel(
    const float* __restrict__ bke, const float* __restrict__ Weo,
    const float* __restrict__ beo, float* __restrict__ biasfold)
{
    int d = blockIdx.x * 128 + threadIdx.x;
    float acc = beo[d];
    for (int h = 0; h < Ht; h++)
        #pragma unroll
        for (int c = 0; c < 32; c++)
            acc += bke[c] * Weo[(size_t)(h * 32 + c) * Dt + d];
    biasfold[d] = acc;
}

// bcomb = bo + bfold @ Wo_bot
__global__ __launch_bounds__(128) void bcomb_kernel(
    const float* __restrict__ bfold, const float* __restrict__ Wo,
    const float* __restrict__ bo, float* __restrict__ bcomb)
{
    int d = blockIdx.x * 128 + threadIdx.x;
    float acc = bo[d];
    for (int e = 0; e < Dt; e++)
        acc += bfold[e] * Wo[(size_t)(Dt + e) * Dt + d];
    bcomb[d] = acc;
}

// ---------------- tf32 tensor-core GEMM ----------------
template<int TBM, int TBN, int WM, int WN, bool TRANSB>
__global__ __launch_bounds__(256, 1) void gemm_tf32_kernel(
    const float* __restrict__ A, const float* __restrict__ Bm, float* __restrict__ C,
    int K, int lda, int ldb, int ldc,
    int batch2,
    long long sA1, long long sA2, long long sB1, long long sB2,
    long long sC1, long long sC2,
    float alpha, const float* __restrict__ bias,
    const float* __restrict__ addend, int ldadd,
    int accumulate, int act_gelu)
{
    constexpr int BK = 32;
    constexpr int WNC = TBN / WN;
    constexpr int MF = WM / 16;
    constexpr int NF = WN / 8;
    constexpr int LDA_S = BK + 4;
    constexpr int LDB_S = TRANSB ? (BK + 4) : (TBN + 8);
    constexpr int BS_ROWS = TRANSB ? TBN : BK;
    constexpr int A_IT = TBM / 32;
    constexpr int B_IT = TRANSB ? (TBN / 32) : ((BK * TBN) / 1024);

    extern __shared__ float smem[];
    float* As = smem;
    float* Bs = smem + 2 * TBM * LDA_S;

    int z = blockIdx.z;
    int z1 = z / batch2, z2 = z % batch2;
    A  += z1 * sA1 + z2 * sA2;
    Bm += z1 * sB1 + z2 * sB2;
    C  += z1 * sC1 + z2 * sC2;

    const int m_blk = blockIdx.y * TBM;
    const int n_blk = blockIdx.x * TBN;

    const int tid = threadIdx.x;
    const int warp = tid >> 5, lane = tid & 31;
    const int g = lane >> 2, tig = lane & 3;
    const int wm = warp / WNC, wn = warp % WNC;
    const int m0 = wm * WM, n0 = wn * WN;

    float4 ra[A_IT], rb[B_IT];

    auto loadA = [&](int k0) {
        #pragma unroll
        for (int it = 0; it < A_IT; it++) {
            int idx = tid + it * 256;
            int r = idx >> 3, kq = (idx & 7) << 2;
            ra[it] = *(const float4*)&A[(size_t)(m_blk + r) * lda + k0 + kq];
        }
    };
    auto storeA = [&](int s) {
        #pragma unroll
        for (int it = 0; it < A_IT; it++) {
            int idx = tid + it * 256;
            int r = idx >> 3, kq = (idx & 7) << 2;
            float4 v = ra[it];
            v.x = f2tf(v.x); v.y = f2tf(v.y); v.z = f2tf(v.z); v.w = f2tf(v.w);
            *(float4*)&As[(s * TBM + r) * LDA_S + kq] = v;
        }
    };
    auto loadB = [&](int k0) {
        #pragma unroll
        for (int it = 0; it < B_IT; it++) {
            int idx = tid + it * 256;
            if (TRANSB) {
                int r = idx >> 3, kq = (idx & 7) << 2;
                rb[it] = *(const float4*)&Bm[(size_t)(n_blk + r) * ldb + k0 + kq];
            } else {
                int r = idx / (TBN / 4), c = (idx % (TBN / 4)) << 2;
                rb[it] = *(const float4*)&Bm[(size_t)(k0 + r) * ldb + n_blk + c];
            }
        }
    };
    auto storeB = [&](int s) {
        #pragma unroll
        for (int it = 0; it < B_IT; it++) {
            int idx = tid + it * 256;
            float4 v = rb[it];
            v.x = f2tf(v.x); v.y = f2tf(v.y); v.z = f2tf(v.z); v.w = f2tf(v.w);
            if (TRANSB) {
                int r = idx >> 3, kq = (idx & 7) << 2;
                *(float4*)&Bs[(s * BS_ROWS + r) * LDB_S + kq] = v;
            } else {
                int r = idx / (TBN / 4), c = (idx % (TBN / 4)) << 2;
                *(float4*)&Bs[(s * BS_ROWS + r) * LDB_S + c] = v;
            }
        }
    };

    float acc[MF][NF][4];
    #pragma unroll
    for (int i = 0; i < MF; i++)
        #pragma unroll
        for (int j = 0; j < NF; j++)
            #pragma unroll
            for (int q = 0; q < 4; q++) acc[i][j][q] = 0.0f;

    loadA(0); loadB(0);
    storeA(0); storeB(0);
    __syncthreads();

    const int nk = K / BK;
    for (int kt = 0; kt < nk; kt++) {
        int s = kt & 1;
        if (kt + 1 < nk) { loadA((kt + 1) * BK); loadB((kt + 1) * BK); }

        #pragma unroll
        for (int ks = 0; ks < 4; ks++) {
            int kb = ks * 8;
            uint32_t afr[MF][4], bfr[NF][2];
            #pragma unroll
            for (int i = 0; i < MF; i++) {
                const float* ap = &As[(s * TBM + m0 + i * 16) * LDA_S + kb];
                afr[i][0] = __float_as_uint(ap[(size_t)g * LDA_S + tig]);
                afr[i][1] = __float_as_uint(ap[(size_t)(g + 8) * LDA_S + tig]);
                afr[i][2] = __float_as_uint(ap[(size_t)g * LDA_S + tig + 4]);
                afr[i][3] = __float_as_uint(ap[(size_t)(g + 8) * LDA_S + tig + 4]);
            }
            #pragma unroll
            for (int j = 0; j < NF; j++) {
                if (TRANSB) {
                    const float* bp = &Bs[(s * BS_ROWS + n0 + j * 8 + g) * LDB_S + kb];
                    bfr[j][0] = __float_as_uint(bp[tig]);
                    bfr[j][1] = __float_as_uint(bp[tig + 4]);
                } else {
                    const float* bp = &Bs[(s * BS_ROWS + kb) * LDB_S + n0 + j * 8 + g];
                    bfr[j][0] = __float_as_uint(bp[(size_t)tig * LDB_S]);
                    bfr[j][1] = __float_as_uint(bp[(size_t)(tig + 4) * LDB_S]);
                }
            }
            #pragma unroll
            for (int i = 0; i < MF; i++)
                #pragma unroll
                for (int j = 0; j < NF; j++)
                    mma_tf32(acc[i][j], afr[i], bfr[j]);
        }

        if (kt + 1 < nk) { storeA(s ^ 1); storeB(s ^ 1); }
        __syncthreads();
    }

    #pragma unroll
    for (int i = 0; i < MF; i++) {
        int row0 = m_blk + m0 + i * 16 + g;
        #pragma unroll
        for (int half = 0; half < 2; half++) {
            int row = row0 + half * 8;
            size_t roff = (size_t)row * ldc;
            #pragma unroll
            for (int j = 0; j < NF; j++) {
                int col = n_blk + n0 + j * 8 + tig * 2;
                float v0 = acc[i][j][half * 2 + 0] * alpha;
                float v1 = acc[i][j][half * 2 + 1] * alpha;
                if (bias)   { v0 += bias[col]; v1 += bias[col + 1]; }
                if (addend) {
                    const float* ad = &addend[(size_t)row * ldadd + col];
                    v0 += ad[0]; v1 += ad[1];
                }
                if (accumulate) { v0 += C[roff + col]; v1 += C[roff + col + 1]; }
                if (act_gelu)   { v0 = gelu_f(v0); v1 = gelu_f(v1); }
                float2 o = make_float2(v0, v1);
                *(float2*)&C[roff + col] = o;
            }
        }
    }
}

// ---------------- fused edge-bias + softmax: block per (b,i), all 8 heads ----------------
__global__ __launch_bounds__(256) void softmax_bias_kernel(
    float* __restrict__ attn, const float4* __restrict__ edge4,
    const float* __restrict__ eg, const float* __restrict__ eb,
    const float* __restrict__ Web, const float* __restrict__ beb,
    const unsigned char* __restrict__ mask)
{
    __shared__ float sbias[Nt];
    int bi = blockIdx.x;
    int b = bi / Nt, i = bi % Nt;
    int t = threadIdx.x;
    int l8 = t & 7;
    int rgrp = t >> 3;                  // 0..31

    float4 g4 = __ldg(&((const float4*)eg)[l8]);
    float4 b4 = __ldg(&((const float4*)eb)[l8]);
    float4 wb = __ldg(&((const float4*)Web)[l8]);
    float bb = __ldg(beb);

    // phase 1: bias[j] = (LN(edge[b,i,j,:]) . Web + beb) / sqrt(2)
    #pragma unroll
    for (int pp = 0; pp < 12; pp++) {
        int j = pp * 32 + rgrp;
        long long pos = (long long)bi * Nt + j;
        float4 e = edge4[pos * 8 + l8];
        float s = e.x + e.y + e.z + e.w;
        s += __shfl_xor_sync(0xffffffffu, s, 4);
        s += __shfl_xor_sync(0xffffffffu, s, 2);
        s += __shfl_xor_sync(0xffffffffu, s, 1);
        float mean = s * (1.0f / 32.0f);
        float4 d = make_float4(e.x - mean, e.y - mean, e.z - mean, e.w - mean);
        float vq = d.x*d.x + d.y*d.y + d.z*d.z + d.w*d.w;
        vq += __shfl_xor_sync(0xffffffffu, vq, 4);
        vq += __shfl_xor_sync(0xffffffffu, vq, 2);
        vq += __shfl_xor_sync(0xffffffffu, vq, 1);
        float inv = rsqrtf(vq * (1.0f / 32.0f) + 1e-5f);
        float nex = d.x * inv * g4.x + b4.x;
        float ney = d.y * inv * g4.y + b4.y;
        float nez = d.z * inv * g4.z + b4.z;
        float new_ = d.w * inv * g4.w + b4.w;
        float pb = nex*wb.x + ney*wb.y + nez*wb.z + new_*wb.w;
        pb += __shfl_xor_sync(0xffffffffu, pb, 4);
        pb += __shfl_xor_sync(0xffffffffu, pb, 2);
        pb += __shfl_xor_sync(0xffffffffu, pb, 1);
        if (l8 == 0) sbias[j] = (pb + bb) * 0.70710678118654752f;
    }
    __syncthreads();

    // phase 2: one warp per head
    int warp = t >> 5, lane = t & 31;
    float* sp = attn + (((size_t)(b * Ht + warp)) * Nt + i) * Nt;
    const unsigned char* mp = mask + (size_t)bi * Nt;

    float v[12];
    float mx = -INFINITY;
    #pragma unroll
    for (int r = 0; r < 12; r++) {
        int j = lane + r * 32;
        float s = sp[j] + sbias[j];
        if (mp[j]) s = -INFINITY;
        v[r] = s;
        mx = fmaxf(mx, s);
    }
    #pragma unroll
    for (int o = 16; o; o >>= 1) mx = fmaxf(mx, __shfl_xor_sync(0xffffffffu, mx, o));
    float sum = 0.0f;
    #pragma unroll
    for (int r = 0; r < 12; r++) { v[r] = __expf(v[r] - mx); sum += v[r]; }
    #pragma unroll
    for (int o = 16; o; o >>= 1) sum += __shfl_xor_sync(0xffffffffu, sum, o);
    float invs = 1.0f / sum;
    #pragma unroll
    for (int r = 0; r < 12; r++) sp[lane + r * 32] = v[r] * invs;
}

// ---------------- ectx_raw: tensor-core contraction attn x LN(edge), inline LN ----------------
// block = (b,i), 128 threads. cat[bi][512 + h*32+c] = sum_j attn[b,h,i,j]*ne[b,i,j,c]
__global__ __launch_bounds__(128) void ectx_raw_kernel(
    const float* __restrict__ attn, const float4* __restrict__ edge4,
    const float* __restrict__ eg, const float* __restrict__ eb,
    float* __restrict__ cat)
{
    constexpr int LDAS = 388;          // [16][388] (rows 8..15 garbage, outputs discarded)
    constexpr int LDBS = 40;           // [128][40]
    __shared__ float sA[16 * LDAS];
    __shared__ float sB[128 * LDBS];

    int bi = blockIdx.x;               // b*N + i
    int b = bi / Nt, i = bi % Nt;
    int t = threadIdx.x;
    int warp = t >> 5, lane = t & 31;
    int g = lane >> 2, tig = lane & 3;
    int n0 = warp * 8;
    int l8 = t & 7;
    int rgrp = t >> 3;                 // 0..15

    // stage attn rows (8 x 384), tf32-rounded
    #pragma unroll
    for (int it = 0; it < 24; it++) {
        int idx = t + it * 128;
        int h = idx / Nt, j = idx % Nt;
        sA[h * LDAS + j] = f2tf(attn[(((size_t)(b * Ht + h)) * Nt + i) * Nt + j]);
    }

    float4 g4 = __ldg(&((const float4*)eg)[l8]);
    float4 b4 = __ldg(&((const float4*)eb)[l8]);

    float acc[4] = {0.0f, 0.0f, 0.0f, 0.0f};

    for (int ch = 0; ch < 3; ch++) {
        __syncthreads();
        // stage ne chunk: 128 j-rows x 32 ch, LN computed inline
        #pragma unroll
        for (int pp = 0; pp < 8; pp++) {
            int jr = pp * 16 + rgrp;
            long long pos = (long long)bi * Nt + ch * 128 + jr;
            float4 e = edge4[pos * 8 + l8];
            float s = e.x + e.y + e.z + e.w;
            s += __shfl_xor_sync(0xffffffffu, s, 4);
            s += __shfl_xor_sync(0xffffffffu, s, 2);
            s += __shfl_xor_sync(0xffffffffu, s, 1);
            float mean = s * (1.0f / 32.0f);
            float4 d = make_float4(e.x - mean, e.y - mean, e.z - mean, e.w - mean);
            float vq = d.x*d.x + d.y*d.y + d.z*d.z + d.w*d.w;
            vq += __shfl_xor_sync(0xffffffffu, vq, 4);
            vq += __shfl_xor_sync(0xffffffffu, vq, 2);
            vq += __shfl_xor_sync(0xffffffffu, vq, 1);
            float inv = rsqrtf(vq * (1.0f / 32.0f) + 1e-5f);
            float4 ne;
            ne.x = f2tf(d.x * inv * g4.x + b4.x);
            ne.y = f2tf(d.y * inv * g4.y + b4.y);
            ne.z = f2tf(d.z * inv * g4.z + b4.z);
            ne.w = f2tf(d.w * inv * g4.w + b4.w);
            *(float4*)&sB[jr * LDBS + l8 * 4] = ne;
        }
        __syncthreads();

        #pragma unroll
        for (int k8 = 0; k8 < 16; k8++) {
            int kb = k8 * 8;
            int kg = ch * 128 + kb;
            uint32_t afr[4], bfr[2];
            afr[0] = __float_as_uint(sA[g * LDAS + kg + tig]);
            afr[1] = __float_as_uint(sA[(g + 8) * LDAS + kg + tig]);
            afr[2] = __float_as_uint(sA[g * LDAS + kg + tig + 4]);
            afr[3] = __float_as_uint(sA[(g + 8) * LDAS + kg + tig + 4]);
            bfr[0] = __float_as_uint(sB[(kb + tig) * LDBS + n0 + g]);
            bfr[1] = __float_as_uint(sB[(kb + tig + 4) * LDBS + n0 + g]);
            mma_tf32(acc, afr, bfr);
        }
    }

    // rows 0..7 valid (g = h)
    float2 o = make_float2(acc[0], acc[1]);
    *(float2*)&cat[(size_t)bi * 768 + 512 + g * DEt + n0 + tig * 2] = o;
}

// ---------------- launch ----------------
extern "C" void kernel_launch(void* const* d_in, const int* in_sizes, int n_in,
                              void* d_out, int out_size)
{
    const float* x      = (const float*)d_in[0];
    const float* edge   = (const float*)d_in[1];
    const unsigned char* mask = (const unsigned char*)d_in[2];
    const float* ln_a_g = (const float*)d_in[3];
    const float* ln_a_b = (const float*)d_in[4];
    const float* ln_e_g = (const float*)d_in[5];
    const float* ln_e_b = (const float*)d_in[6];
    const float* Wq = (const float*)d_in[7];   const float* bq = (const float*)d_in[8];
    const float* Wk = (const float*)d_in[9];   const float* bk = (const float*)d_in[10];
    const float* Wv = (const float*)d_in[11];  const float* bv = (const float*)d_in[12];
    const float* Wke = (const float*)d_in[13]; const float* bke = (const float*)d_in[14];
    const float* Web = (const float*)d_in[15]; const float* beb = (const float*)d_in[16];
    const float* Weo = (const float*)d_in[17]; const float* beo = (const float*)d_in[18];
    const float* Wo  = (const float*)d_in[19]; const float* bo  = (const float*)d_in[20];
    const float* ln_f_g = (const float*)d_in[21];
    const float* ln_f_b = (const float*)d_in[22];
    const float* W1 = (const float*)d_in[23];  const float* b1 = (const float*)d_in[24];
    const float* W2 = (const float*)d_in[25];  const float* b2 = (const float*)d_in[26];
    float* out = (float*)d_out;

    float* base;
    cudaGetSymbolAddress((void**)&base, g_scratch);
    float* nx    = base + OFF_NX;
    float* qkv   = base + OFF_QKV;       // [3072][1536] = [q|k|v]
    float* attn  = base + OFF_ATTN;
    float* cat   = base + OFF_CAT;       // [3072][768] = [ctx | raw]
    float* x1    = base + OFF_X1;
    float* nx2   = base + OFF_NX2;
    float* h1    = base + OFF_H1;
    float* Wqkv  = base + OFF_WQKV;
    float* bqkv  = base + OFF_BQKV;
    float* Wfold = base + OFF_WFOLD;
    float* bfold = base + OFF_BFOLD;
    float* Wcat  = base + OFF_WCAT;      // [768][512] = [Wo_top ; Wcomb]
    float* bcomb = base + OFF_BCOMB;

    auto GA = gemm_tf32_kernel<128, 128, 64, 32, false>;   // generic NN
    auto GT = gemm_tf32_kernel<128, 128, 64, 32, true>;    // NT (scores)
    auto GV = gemm_tf32_kernel<128, 64, 32, 32, false>;    // attn @ V

    constexpr int SMEM_GA = (2 * 128 * 36 + 2 * 32 * 136) * 4;   // 71680
    constexpr int SMEM_GT = (2 * 128 * 36 + 2 * 128 * 36) * 4;   // 73728
    constexpr int SMEM_GV = (2 * 128 * 36 + 2 * 32 * 72) * 4;    // 55296
    cudaFuncSetAttribute(GA, cudaFuncAttributeMaxDynamicSharedMemorySize, SMEM_GA);
    cudaFuncSetAttribute(GT, cudaFuncAttributeMaxDynamicSharedMemorySize, SMEM_GT);
    cudaFuncSetAttribute(GV, cudaFuncAttributeMaxDynamicSharedMemorySize, SMEM_GV);

    // 0. packing + folding (tiny)
    pack_kernel<<<Dt, 256>>>(Wq, Wk, Wv, bq, bk, bv, Wo, Wqkv, bqkv, Wcat);
    fold_w_kernel<<<dim3(Ht, Dt / 128), 128>>>(Wke, Weo, Wfold);
    fold_b_kernel<<<Dt / 128, 128>>>(bke, Weo, beo, bfold);
    bcomb_kernel<<<Dt / 128, 128>>>(bfold, Wo, bo, bcomb);
    // Wcomb = Wfold @ Wo_bot -> Wcat rows [512,768)
    GA<<<dim3(Dt / 128, 2, 1), 256, SMEM_GA>>>(Wfold, Wo + (size_t)Dt * Dt,
        Wcat + (size_t)Dt * Dt, Dt, Dt, Dt, Dt,
        1, 0, 0, 0, 0, 0, 0, 1.0f, nullptr, nullptr, 0, 0, 0);

    // 1. LN(x)
    ln512_kernel<<<BNr, 128>>>(x, ln_a_g, ln_a_b, nx);

    // 2. fused qkv projection: (3072,512)@(512,1536)
    dim3 gqkv(1536 / 128, BNr / 128, 1);
    GA<<<gqkv, 256, SMEM_GA>>>(nx, Wqkv, qkv, Dt, Dt, 1536, 1536,
        1, 0, 0, 0, 0, 0, 0, 1.0f, bqkv, nullptr, 0, 0, 0);

    // 3. scores = alpha * Q @ K^T, batched over (b,h)
    dim3 gsc(Nt / 128, Nt / 128, Bt * Ht);
    GT<<<gsc, 256, SMEM_GT>>>(qkv, qkv + 512, attn, DKt, 1536, 1536, Nt,
        Ht, (long long)Nt * 1536, 64, (long long)Nt * 1536, 64,
        (long long)Ht * NNt, (long long)NNt,
        0.08838834764831845f, nullptr, nullptr, 0, 0, 0);

    // 4. fused edge-bias + softmax + mask
    softmax_bias_kernel<<<BNr, 256>>>(attn, (const float4*)edge, ln_e_g, ln_e_b,
                                      Web, beb, mask);

    // 5. ctx half of cat = attn @ V
    dim3 gcx(1, Nt / 128, Bt * Ht);
    GV<<<gcx, 256, SMEM_GV>>>(attn, qkv + 1024, cat, Nt, Nt, 1536, 768,
        Ht, (long long)Ht * NNt, (long long)NNt, (long long)Nt * 1536, 64,
        (long long)Nt * 768, 64,
        1.0f, nullptr, nullptr, 0, 0, 0);

    // 6. raw half of cat = attn x LN(edge) contraction (inline LN, tensor cores)
    ectx_raw_kernel<<<BNr, 128>>>(attn, (const float4*)edge, ln_e_g, ln_e_b, cat);

    // 7. x1 = x + cat @ Wcat + bcomb : (3072,768)@(768,512)
    dim3 gx1(Dt / 128, BNr / 128, 1);
    GA<<<gx1, 256, SMEM_GA>>>(cat, Wcat, x1, 768, 768, Dt, Dt,
        1, 0, 0, 0, 0, 0, 0, 1.0f, bcomb, x, Dt, 0, 0);

    // 8. nx2 = LN(x1)
    ln512_kernel<<<BNr, 128>>>(x1, ln_f_g, ln_f_b, nx2);

    // 9. h1 = gelu(nx2 @ W1 + b1)
    dim3 gf1(DFt / 128, BNr / 128, 1);
    GA<<<gf1, 256, SMEM_GA>>>(nx2, W1, h1, Dt, Dt, DFt, DFt,
        1, 0, 0, 0, 0, 0, 0, 1.0f, b1, nullptr, 0, 0, 1);

    // 10. out = x1 + h1 @ W2 + b2
    dim3 gf2(Dt / 128, BNr / 128, 1);
    GA<<<gf2, 256, SMEM_GA>>>(h1, W2, out, DFt, DFt, Dt, Dt,
        1, 0, 0, 0, 0, 0, 0, 1.0f, b2, x1, Dt, 0, 0);

    (void)in_sizes; (void)n_in; (void)out_size;
}

// round 6
// speedup vs baseline: 3.1293x; 1.0030x over previous
#include <cuda_runtime.h>
#include <cuda_bf16.h>
#include <math.h>
#include <stdint.h>

// ---------------- problem constants ----------------
#define Bt   8
#define Nt   384
#define Dt   512
#define Ht   8
#define DEt  32
#define DFt  2048
#define DKt  64
#define BNr  (Bt*Nt)            // 3072
#define NNt  (Nt*Nt)            // 147456

// scratch layout (floats)
#define OFF_NX     0LL
#define OFF_QKV    (OFF_NX    + (long long)BNr*Dt)
#define OFF_ATTN   (OFF_QKV   + (long long)BNr*3*Dt)
#define OFF_CAT    (OFF_ATTN  + (long long)Bt*Ht*NNt)   // [BNr][768] = [ctx | raw]
#define OFF_X1     (OFF_CAT   + (long long)BNr*768)
#define OFF_NX2    (OFF_X1    + (long long)BNr*Dt)
#define OFF_H1     (OFF_NX2   + (long long)BNr*Dt)
#define OFF_WQKV   (OFF_H1    + (long long)BNr*DFt)
#define OFF_BQKV   (OFF_WQKV  + (long long)Dt*3*Dt)
#define OFF_WFOLD  (OFF_BQKV  + 3*Dt)
#define OFF_BFOLD  (OFF_WFOLD + (long long)Ht*DEt*Dt)
#define OFF_WCAT   (OFF_BFOLD + Dt)                      // [768][512]
#define OFF_BCOMB  (OFF_WCAT  + (long long)768*Dt)
#define SCRATCH_TOTAL (OFF_BCOMB + Dt)

static __device__ float g_scratch[SCRATCH_TOTAL];

// ---------------- helpers ----------------
__device__ __forceinline__ float gelu_f(float v) {
    float t3 = v * v * v;
    return 0.5f * v * (1.0f + tanhf(0.7978845608028654f * (v + 0.044715f * t3)));
}

__device__ __forceinline__ float f2tf(float x) {
    uint32_t u;
    asm("cvt.rna.tf32.f32 %0, %1;" : "=r"(u) : "f"(x));
    return __uint_as_float(u);
}

__device__ __forceinline__ void mma_tf32(float* c, const uint32_t* a, const uint32_t* b) {
    asm volatile(
        "mma.sync.aligned.m16n8k8.row.col.f32.tf32.tf32.f32 "
        "{%0,%1,%2,%3}, {%4,%5,%6,%7}, {%8,%9}, {%0,%1,%2,%3};\n"
        : "+f"(c[0]), "+f"(c[1]), "+f"(c[2]), "+f"(c[3])
        : "r"(a[0]), "r"(a[1]), "r"(a[2]), "r"(a[3]), "r"(b[0]), "r"(b[1]));
}

__device__ __forceinline__ float blockReduce128(float v, bool isMax, float* sh) {
    #pragma unroll
    for (int o = 16; o; o >>= 1) {
        float o2 = __shfl_xor_sync(0xffffffffu, v, o);
        v = isMax ? fmaxf(v, o2) : v + o2;
    }
    __syncthreads();
    if ((threadIdx.x & 31) == 0) sh[threadIdx.x >> 5] = v;
    __syncthreads();
    float r = sh[0];
    #pragma unroll
    for (int k = 1; k < 4; k++) r = isMax ? fmaxf(r, sh[k]) : r + sh[k];
    return r;
}

// ---------------- LayerNorm over 512 cols ----------------
__global__ __launch_bounds__(128) void ln512_kernel(
    const float* __restrict__ in, const float* __restrict__ g,
    const float* __restrict__ b, float* __restrict__ out)
{
    __shared__ float sh[4];
    int row = blockIdx.x;
    int t = threadIdx.x;
    const float4* inr = (const float4*)(in + (size_t)row * Dt);
    float4 v = inr[t];
    float s  = v.x + v.y + v.z + v.w;
    float sq = v.x*v.x + v.y*v.y + v.z*v.z + v.w*v.w;
    float tot = blockReduce128(s, false, sh);
    __syncthreads();
    float totq = blockReduce128(sq, false, sh);
    float mean = tot * (1.0f / Dt);
    float var  = totq * (1.0f / Dt) - mean * mean;
    float inv  = rsqrtf(var + 1e-5f);
    float4 gg = ((const float4*)g)[t];
    float4 bb = ((const float4*)b)[t];
    float4 o;
    o.x = (v.x - mean) * inv * gg.x + bb.x;
    o.y = (v.y - mean) * inv * gg.y + bb.y;
    o.z = (v.z - mean) * inv * gg.z + bb.z;
    o.w = (v.w - mean) * inv * gg.w + bb.w;
    ((float4*)(out + (size_t)row * Dt))[t] = o;
}

// ---------------- pack: Wqkv, bqkv, Wcat(top=Wo_top) ----------------
__global__ __launch_bounds__(256) void pack_kernel(
    const float* __restrict__ Wq, const float* __restrict__ Wk,
    const float* __restrict__ Wv,
    const float* __restrict__ bq, const float* __restrict__ bk,
    const float* __restrict__ bv,
    const float* __restrict__ Wo,
    float* __restrict__ Wqkv, float* __restrict__ bqkv, float* __restrict__ Wcat)
{
    int k = blockIdx.x;
    for (int n = threadIdx.x; n < Dt; n += 256) {
        Wqkv[(size_t)k * 1536 + n]        = Wq[(size_t)k * Dt + n];
        Wqkv[(size_t)k * 1536 + 512 + n]  = Wk[(size_t)k * Dt + n];
        Wqkv[(size_t)k * 1536 + 1024 + n] = Wv[(size_t)k * Dt + n];
        Wcat[(size_t)k * Dt + n]          = Wo[(size_t)k * Dt + n];
    }
    if (k == 0) {
        for (int n = threadIdx.x; n < Dt; n += 256) {
            bqkv[n] = bq[n]; bqkv[512 + n] = bk[n]; bqkv[1024 + n] = bv[n];
        }
    }
}

// ---------------- fold kernels ----------------
__global__ __launch_bounds__(128) void fold_w_kernel(
    const float* __restrict__ Wke, const float* __restrict__ Weo,
    float* __restrict__ Wfold)
{
    __shared__ float sK[32 * 32];
    int t = threadIdx.x;
    for (int i = t; i < 1024; i += 128) sK[i] = Wke[i];
    __syncthreads();
    int h = blockIdx.x;
    int d = blockIdx.y * 128 + t;
    float wcol[32];
    #pragma unroll
    for (int c = 0; c < 32; c++)
        wcol[c] = Weo[(size_t)(h * 32 + c) * Dt + d];
    for (int k = 0; k < 32; k++) {
        float acc = 0.0f;
        #pragma unroll
        for (int c = 0; c < 32; c++) acc += sK[k * 32 + c] * wcol[c];
        Wfold[(size_t)(h * 32 + k) * Dt + d] = acc;
    }
}

// biasfold[d] = beo[d] + sum_e bke[e&31] * Weo[e*512 + d], e in [0,256)
__global__ __launch_bounds__(256) void fold_b_kernel(
    const float* __restrict__ bke, const float* __restrict__ Weo,
    const float* __restrict__ beo, float* __restrict__ biasfold)
{
    int t = threadIdx.x;
    int out = blockIdx.x * 64 + (t >> 2);
    int sub = t & 3;
    float acc = 0.0f;
    for (int e = sub; e < Ht * DEt; e += 4)
        acc += bke[e & 31] * Weo[(size_t)e * Dt + out];
    acc += __shfl_xor_sync(0xffffffffu, acc, 2);
    acc += __shfl_xor_sync(0xffffffffu, acc, 1);
    if (sub == 0) biasfold[out] = beo[out] + acc;
}

// bcomb[d] = bo[d] + sum_e bfold[e] * Wo[(512+e)*512 + d]
__global__ __launch_bounds__(256) void bcomb_kernel(
    const float* __restrict__ bfold, const float* __restrict__ Wo,
    const float* __restrict__ bo, float* __restrict__ bcomb)
{
    int t = threadIdx.x;
    int out = blockIdx.x * 64 + (t >> 2);
    int sub = t & 3;
    float acc = 0.0f;
    for (int e = sub; e < Dt; e += 4)
        acc += bfold[e] * Wo[(size_t)(Dt + e) * Dt + out];
    acc += __shfl_xor_sync(0xffffffffu, acc, 2);
    acc += __shfl_xor_sync(0xffffffffu, acc, 1);
    if (sub == 0) bcomb[out] = bo[out] + acc;
}

// ---------------- tf32 tensor-core GEMM ----------------
template<int TBM, int TBN, int WM, int WN, bool TRANSB>
__global__ __launch_bounds__(256, 1) void gemm_tf32_kernel(
    const float* __restrict__ A, const float* __restrict__ Bm, float* __restrict__ C,
    int K, int lda, int ldb, int ldc,
    int batch2,
    long long sA1, long long sA2, long long sB1, long long sB2,
    long long sC1, long long sC2,
    float alpha, const float* __restrict__ bias,
    const float* __restrict__ addend, int ldadd,
    int accumulate, int act_gelu)
{
    constexpr int BK = 32;
    constexpr int WNC = TBN / WN;
    constexpr int MF = WM / 16;
    constexpr int NF = WN / 8;
    constexpr int LDA_S = BK + 4;
    constexpr int LDB_S = TRANSB ? (BK + 4) : (TBN + 8);
    constexpr int BS_ROWS = TRANSB ? TBN : BK;
    constexpr int A_IT = TBM / 32;
    constexpr int B_IT = TRANSB ? (TBN / 32) : ((BK * TBN) / 1024);

    extern __shared__ float smem[];
    float* As = smem;
    float* Bs = smem + 2 * TBM * LDA_S;

    int z = blockIdx.z;
    int z1 = z / batch2, z2 = z % batch2;
    A  += z1 * sA1 + z2 * sA2;
    Bm += z1 * sB1 + z2 * sB2;
    C  += z1 * sC1 + z2 * sC2;

    const int m_blk = blockIdx.y * TBM;
    const int n_blk = blockIdx.x * TBN;

    const int tid = threadIdx.x;
    const int warp = tid >> 5, lane = tid & 31;
    const int g = lane >> 2, tig = lane & 3;
    const int wm = warp / WNC, wn = warp % WNC;
    const int m0 = wm * WM, n0 = wn * WN;

    float4 ra[A_IT], rb[B_IT];

    auto loadA = [&](int k0) {
        #pragma unroll
        for (int it = 0; it < A_IT; it++) {
            int idx = tid + it * 256;
            int r = idx >> 3, kq = (idx & 7) << 2;
            ra[it] = *(const float4*)&A[(size_t)(m_blk + r) * lda + k0 + kq];
        }
    };
    auto storeA = [&](int s) {
        #pragma unroll
        for (int it = 0; it < A_IT; it++) {
            int idx = tid + it * 256;
            int r = idx >> 3, kq = (idx & 7) << 2;
            float4 v = ra[it];
            v.x = f2tf(v.x); v.y = f2tf(v.y); v.z = f2tf(v.z); v.w = f2tf(v.w);
            *(float4*)&As[(s * TBM + r) * LDA_S + kq] = v;
        }
    };
    auto loadB = [&](int k0) {
        #pragma unroll
        for (int it = 0; it < B_IT; it++) {
            int idx = tid + it * 256;
            if (TRANSB) {
                int r = idx >> 3, kq = (idx & 7) << 2;
                rb[it] = *(const float4*)&Bm[(size_t)(n_blk + r) * ldb + k0 + kq];
            } else {
                int r = idx / (TBN / 4), c = (idx % (TBN / 4)) << 2;
                rb[it] = *(const float4*)&Bm[(size_t)(k0 + r) * ldb + n_blk + c];
            }
        }
    };
    auto storeB = [&](int s) {
        #pragma unroll
        for (int it = 0; it < B_IT; it++) {
            int idx = tid + it * 256;
            float4 v = rb[it];
            v.x = f2tf(v.x); v.y = f2tf(v.y); v.z = f2tf(v.z); v.w = f2tf(v.w);
            if (TRANSB) {
                int r = idx >> 3, kq = (idx & 7) << 2;
                *(float4*)&Bs[(s * BS_ROWS + r) * LDB_S + kq] = v;
            } else {
                int r = idx / (TBN / 4), c = (idx % (TBN / 4)) << 2;
                *(float4*)&Bs[(s * BS_ROWS + r) * LDB_S + c] = v;
            }
        }
    };

    float acc[MF][NF][4];
    #pragma unroll
    for (int i = 0; i < MF; i++)
        #pragma unroll
        for (int j = 0; j < NF; j++)
            #pragma unroll
            for (int q = 0; q < 4; q++) acc[i][j][q] = 0.0f;

    loadA(0); loadB(0);
    storeA(0); storeB(0);
    __syncthreads();

    const int nk = K / BK;
    for (int kt = 0; kt < nk; kt++) {
        int s = kt & 1;
        if (kt + 1 < nk) { loadA((kt + 1) * BK); loadB((kt + 1) * BK); }

        #pragma unroll
        for (int ks = 0; ks < 4; ks++) {
            int kb = ks * 8;
            uint32_t afr[MF][4], bfr[NF][2];
            #pragma unroll
            for (int i = 0; i < MF; i++) {
                const float* ap = &As[(s * TBM + m0 + i * 16) * LDA_S + kb];
                afr[i][0] = __float_as_uint(ap[(size_t)g * LDA_S + tig]);
                afr[i][1] = __float_as_uint(ap[(size_t)(g + 8) * LDA_S + tig]);
                afr[i][2] = __float_as_uint(ap[(size_t)g * LDA_S + tig + 4]);
                afr[i][3] = __float_as_uint(ap[(size_t)(g + 8) * LDA_S + tig + 4]);
            }
            #pragma unroll
            for (int j = 0; j < NF; j++) {
                if (TRANSB) {
                    const float* bp = &Bs[(s * BS_ROWS + n0 + j * 8 + g) * LDB_S + kb];
                    bfr[j][0] = __float_as_uint(bp[tig]);
                    bfr[j][1] = __float_as_uint(bp[tig + 4]);
                } else {
                    const float* bp = &Bs[(s * BS_ROWS + kb) * LDB_S + n0 + j * 8 + g];
                    bfr[j][0] = __float_as_uint(bp[(size_t)tig * LDB_S]);
                    bfr[j][1] = __float_as_uint(bp[(size_t)(tig + 4) * LDB_S]);
                }
            }
            #pragma unroll
            for (int i = 0; i < MF; i++)
                #pragma unroll
                for (int j = 0; j < NF; j++)
                    mma_tf32(acc[i][j], afr[i], bfr[j]);
        }

        if (kt + 1 < nk) { storeA(s ^ 1); storeB(s ^ 1); }
        __syncthreads();
    }

    #pragma unroll
    for (int i = 0; i < MF; i++) {
        int row0 = m_blk + m0 + i * 16 + g;
        #pragma unroll
        for (int half = 0; half < 2; half++) {
            int row = row0 + half * 8;
            size_t roff = (size_t)row * ldc;
            #pragma unroll
            for (int j = 0; j < NF; j++) {
                int col = n_blk + n0 + j * 8 + tig * 2;
                float v0 = acc[i][j][half * 2 + 0] * alpha;
                float v1 = acc[i][j][half * 2 + 1] * alpha;
                if (bias)   { v0 += bias[col]; v1 += bias[col + 1]; }
                if (addend) {
                    const float* ad = &addend[(size_t)row * ldadd + col];
                    v0 += ad[0]; v1 += ad[1];
                }
                if (accumulate) { v0 += C[roff + col]; v1 += C[roff + col + 1]; }
                if (act_gelu)   { v0 = gelu_f(v0); v1 = gelu_f(v1); }
                float2 o = make_float2(v0, v1);
                *(float2*)&C[roff + col] = o;
            }
        }
    }
}

// ---------------- fused edge: LN + bias + softmax + ectx contraction ----------------
// block per (b,i), 256 threads, dynamic smem.
// Stages ne=LN(edge[b,i,:,:]) tf32 in shared once; computes bias; softmaxes all 8
// heads (writes normalized attn to gmem + tf32 to shared); contracts attn x ne.
__global__ __launch_bounds__(256) void edge_attn_kernel(
    float* __restrict__ attn, const float4* __restrict__ edge4,
    const float* __restrict__ eg, const float* __restrict__ eb,
    const float* __restrict__ Web, const float* __restrict__ beb,
    const unsigned char* __restrict__ mask, float* __restrict__ cat)
{
    constexpr int LDAS = 388;          // sA [16][388], rows 8..15 unused garbage
    constexpr int LDBS = 40;           // sB [384][40]
    extern __shared__ float smem[];
    float* sA = smem;                  // 6208 floats
    float* sB = smem + 16 * LDAS;      // 15360 floats
    float* sbias = sB + Nt * LDBS;     // 384 floats

    int bi = blockIdx.x;
    int b = bi / Nt, i = bi % Nt;
    int t = threadIdx.x;
    int l8 = t & 7, rgrp = t >> 3;     // 32 position-groups

    float4 g4 = __ldg(&((const float4*)eg)[l8]);
    float4 b4 = __ldg(&((const float4*)eb)[l8]);
    float4 wb = __ldg(&((const float4*)Web)[l8]);
    float bb = __ldg(beb);

    // phase 1: stage ne (tf32) + bias
    #pragma unroll
    for (int pp = 0; pp < 12; pp++) {
        int j = pp * 32 + rgrp;
        float4 e = edge4[((long long)bi * Nt + j) * 8 + l8];
        float s = e.x + e.y + e.z + e.w;
        s += __shfl_xor_sync(0xffffffffu, s, 4);
        s += __shfl_xor_sync(0xffffffffu, s, 2);
        s += __shfl_xor_sync(0xffffffffu, s, 1);
        float mean = s * (1.0f / 32.0f);
        float4 d = make_float4(e.x - mean, e.y - mean, e.z - mean, e.w - mean);
        float vq = d.x*d.x + d.y*d.y + d.z*d.z + d.w*d.w;
        vq += __shfl_xor_sync(0xffffffffu, vq, 4);
        vq += __shfl_xor_sync(0xffffffffu, vq, 2);
        vq += __shfl_xor_sync(0xffffffffu, vq, 1);
        float inv = rsqrtf(vq * (1.0f / 32.0f) + 1e-5f);
        float4 ne;
        ne.x = d.x * inv * g4.x + b4.x;
        ne.y = d.y * inv * g4.y + b4.y;
        ne.z = d.z * inv * g4.z + b4.z;
        ne.w = d.w * inv * g4.w + b4.w;
        float pb = ne.x*wb.x + ne.y*wb.y + ne.z*wb.z + ne.w*wb.w;
        pb += __shfl_xor_sync(0xffffffffu, pb, 4);
        pb += __shfl_xor_sync(0xffffffffu, pb, 2);
        pb += __shfl_xor_sync(0xffffffffu, pb, 1);
        if (l8 == 0) sbias[j] = (pb + bb) * 0.70710678118654752f;
        ne.x = f2tf(ne.x); ne.y = f2tf(ne.y);
        ne.z = f2tf(ne.z); ne.w = f2tf(ne.w);
        *(float4*)&sB[j * LDBS + l8 * 4] = ne;
    }
    __syncthreads();

    // phase 2: softmax, one warp per head; write gmem + staged tf32
    int warp = t >> 5, lane = t & 31;
    float* sp = attn + (((size_t)(b * Ht + warp)) * Nt + i) * Nt;
    const unsigned char* mp = mask + (size_t)bi * Nt;
    float v[12];
    float mx = -INFINITY;
    #pragma unroll
    for (int r = 0; r < 12; r++) {
        int j = lane + r * 32;
        float s = sp[j] + sbias[j];
        if (mp[j]) s = -INFINITY;
        v[r] = s;
        mx = fmaxf(mx, s);
    }
    #pragma unroll
    for (int o = 16; o; o >>= 1) mx = fmaxf(mx, __shfl_xor_sync(0xffffffffu, mx, o));
    float sum = 0.0f;
    #pragma unroll
    for (int r = 0; r < 12; r++) { v[r] = __expf(v[r] - mx); sum += v[r]; }
    #pragma unroll
    for (int o = 16; o; o >>= 1) sum += __shfl_xor_sync(0xffffffffu, sum, o);
    float invs = 1.0f / sum;
    #pragma unroll
    for (int r = 0; r < 12; r++) {
        int j = lane + r * 32;
        float val = v[r] * invs;
        sp[j] = val;
        sA[warp * LDAS + j] = f2tf(val);
    }
    __syncthreads();

    // phase 3: contraction attn(8x384) x ne(384x32), warps 0..3
    if (warp < 4) {
        int g = lane >> 2, tig = lane & 3;
        int n0 = warp * 8;
        float acc[4] = {0.0f, 0.0f, 0.0f, 0.0f};
        #pragma unroll
        for (int k8 = 0; k8 < 48; k8++) {
            int kb = k8 * 8;
            uint32_t afr[4], bfr[2];
            afr[0] = __float_as_uint(sA[g * LDAS + kb + tig]);
            afr[1] = __float_as_uint(sA[(g + 8) * LDAS + kb + tig]);
            afr[2] = __float_as_uint(sA[g * LDAS + kb + tig + 4]);
            afr[3] = __float_as_uint(sA[(g + 8) * LDAS + kb + tig + 4]);
            bfr[0] = __float_as_uint(sB[(kb + tig) * LDBS + n0 + g]);
            bfr[1] = __float_as_uint(sB[(kb + tig + 4) * LDBS + n0 + g]);
            mma_tf32(acc, afr, bfr);
        }
        float2 o = make_float2(acc[0], acc[1]);
        *(float2*)&cat[(size_t)bi * 768 + 512 + g * DEt + n0 + tig * 2] = o;
    }
}

// ---------------- launch ----------------
extern "C" void kernel_launch(void* const* d_in, const int* in_sizes, int n_in,
                              void* d_out, int out_size)
{
    const float* x      = (const float*)d_in[0];
    const float* edge   = (const float*)d_in[1];
    const unsigned char* mask = (const unsigned char*)d_in[2];
    const float* ln_a_g = (const float*)d_in[3];
    const float* ln_a_b = (const float*)d_in[4];
    const float* ln_e_g = (const float*)d_in[5];
    const float* ln_e_b = (const float*)d_in[6];
    const float* Wq = (const float*)d_in[7];   const float* bq = (const float*)d_in[8];
    const float* Wk = (const float*)d_in[9];   const float* bk = (const float*)d_in[10];
    const float* Wv = (const float*)d_in[11];  const float* bv = (const float*)d_in[12];
    const float* Wke = (const float*)d_in[13]; const float* bke = (const float*)d_in[14];
    const float* Web = (const float*)d_in[15]; const float* beb = (const float*)d_in[16];
    const float* Weo = (const float*)d_in[17]; const float* beo = (const float*)d_in[18];
    const float* Wo  = (const float*)d_in[19]; const float* bo  = (const float*)d_in[20];
    const float* ln_f_g = (const float*)d_in[21];
    const float* ln_f_b = (const float*)d_in[22];
    const float* W1 = (const float*)d_in[23];  const float* b1 = (const float*)d_in[24];
    const float* W2 = (const float*)d_in[25];  const float* b2 = (const float*)d_in[26];
    float* out = (float*)d_out;

    float* base;
    cudaGetSymbolAddress((void**)&base, g_scratch);
    float* nx    = base + OFF_NX;
    float* qkv   = base + OFF_QKV;       // [3072][1536] = [q|k|v]
    float* attn  = base + OFF_ATTN;
    float* cat   = base + OFF_CAT;       // [3072][768] = [ctx | raw]
    float* x1    = base + OFF_X1;
    float* nx2   = base + OFF_NX2;
    float* h1    = base + OFF_H1;
    float* Wqkv  = base + OFF_WQKV;
    float* bqkv  = base + OFF_BQKV;
    float* Wfold = base + OFF_WFOLD;
    float* bfold = base + OFF_BFOLD;
    float* Wcat  = base + OFF_WCAT;      // [768][512] = [Wo_top ; Wcomb]
    float* bcomb = base + OFF_BCOMB;

    auto GA = gemm_tf32_kernel<128, 128, 64, 32, false>;   // generic NN
    auto GT = gemm_tf32_kernel<128, 128, 64, 32, true>;    // NT (scores)
    auto GV = gemm_tf32_kernel<128, 64, 32, 32, false>;    // attn @ V

    constexpr int SMEM_GA = (2 * 128 * 36 + 2 * 32 * 136) * 4;   // 71680
    constexpr int SMEM_GT = (2 * 128 * 36 + 2 * 128 * 36) * 4;   // 73728
    constexpr int SMEM_GV = (2 * 128 * 36 + 2 * 32 * 72) * 4;    // 55296
    constexpr int SMEM_EA = (16 * 388 + 384 * 40 + 384) * 4;     // 87808
    cudaFuncSetAttribute(GA, cudaFuncAttributeMaxDynamicSharedMemorySize, SMEM_GA);
    cudaFuncSetAttribute(GT, cudaFuncAttributeMaxDynamicSharedMemorySize, SMEM_GT);
    cudaFuncSetAttribute(GV, cudaFuncAttributeMaxDynamicSharedMemorySize, SMEM_GV);
    cudaFuncSetAttribute(edge_attn_kernel, cudaFuncAttributeMaxDynamicSharedMemorySize, SMEM_EA);

    // 0. packing + folding (all parallel, tiny)
    pack_kernel<<<Dt, 256>>>(Wq, Wk, Wv, bq, bk, bv, Wo, Wqkv, bqkv, Wcat);
    fold_w_kernel<<<dim3(Ht, Dt / 128), 128>>>(Wke, Weo, Wfold);
    fold_b_kernel<<<Dt / 64, 256>>>(bke, Weo, beo, bfold);
    bcomb_kernel<<<Dt / 64, 256>>>(bfold, Wo, bo, bcomb);
    // Wcomb = Wfold @ Wo_bot -> Wcat rows [512,768)
    GA<<<dim3(Dt / 128, 2, 1), 256, SMEM_GA>>>(Wfold, Wo + (size_t)Dt * Dt,
        Wcat + (size_t)Dt * Dt, Dt, Dt, Dt, Dt,
        1, 0, 0, 0, 0, 0, 0, 1.0f, nullptr, nullptr, 0, 0, 0);

    // 1. LN(x)
    ln512_kernel<<<BNr, 128>>>(x, ln_a_g, ln_a_b, nx);

    // 2. fused qkv projection: (3072,512)@(512,1536)
    dim3 gqkv(1536 / 128, BNr / 128, 1);
    GA<<<gqkv, 256, SMEM_GA>>>(nx, Wqkv, qkv, Dt, Dt, 1536, 1536,
        1, 0, 0, 0, 0, 0, 0, 1.0f, bqkv, nullptr, 0, 0, 0);

    // 3. scores = alpha * Q @ K^T, batched over (b,h)
    dim3 gsc(Nt / 128, Nt / 128, Bt * Ht);
    GT<<<gsc, 256, SMEM_GT>>>(qkv, qkv + 512, attn, DKt, 1536, 1536, Nt,
        Ht, (long long)Nt * 1536, 64, (long long)Nt * 1536, 64,
        (long long)Ht * NNt, (long long)NNt,
        0.08838834764831845f, nullptr, nullptr, 0, 0, 0);

    // 4. fused edge LN + bias + softmax + ectx contraction
    edge_attn_kernel<<<BNr, 256, SMEM_EA>>>(attn, (const float4*)edge,
        ln_e_g, ln_e_b, Web, beb, mask, cat);

    // 5. ctx half of cat = attn @ V
    dim3 gcx(1, Nt / 128, Bt * Ht);
    GV<<<gcx, 256, SMEM_GV>>>(attn, qkv + 1024, cat, Nt, Nt, 1536, 768,
        Ht, (long long)Ht * NNt, (long long)NNt, (long long)Nt * 1536, 64,
        (long long)Nt * 768, 64,
        1.0f, nullptr, nullptr, 0, 0, 0);

    // 6. x1 = x + cat @ Wcat + bcomb : (3072,768)@(768,512)
    dim3 gx1(Dt / 128, BNr / 128, 1);
    GA<<<gx1, 256, SMEM_GA>>>(cat, Wcat, x1, 768, 768, Dt, Dt,
        1, 0, 0, 0, 0, 0, 0, 1.0f, bcomb, x, Dt, 0, 0);

    // 7. nx2 = LN(x1)
    ln512_kernel<<<BNr, 128>>>(x1, ln_f_g, ln_f_b, nx2);

    // 8. h1 = gelu(nx2 @ W1 + b1)
    dim3 gf1(DFt / 128, BNr / 128, 1);
    GA<<<gf1, 256, SMEM_GA>>>(nx2, W1, h1, Dt, Dt, DFt, DFt,
        1, 0, 0, 0, 0, 0, 0, 1.0f, b1, nullptr, 0, 0, 1);

    // 9. out = x1 + h1 @ W2 + b2
    dim3 gf2(Dt / 128, BNr / 128, 1);
    GA<<<gf2, 256, SMEM_GA>>>(h1, W2, out, DFt, DFt, Dt, Dt,
        1, 0, 0, 0, 0, 0, 0, 1.0f, b2, x1, Dt, 0, 0);

    (void)in_sizes; (void)n_in; (void)out_size;
}